// round 1
// baseline (speedup 1.0000x reference)
#include <cuda_runtime.h>
#include <cuda_bf16.h>
#include <math_constants.h>

// Problem constants
#define BATCH 4
#define SEQ   2048
#define DMODEL 1024
#define NHEAD 16
#define DK    64
#define MROWS (BATCH * SEQ)   // 8192

// ---------------------------------------------------------------------------
// Scratch (static __device__ arrays; no allocations allowed)
// ---------------------------------------------------------------------------
__device__ float g_Q[MROWS * DMODEL];
__device__ float g_K[MROWS * DMODEL];
__device__ float g_V[MROWS * DMODEL];
__device__ float g_C[MROWS * DMODEL];

// ---------------------------------------------------------------------------
// SGEMM (NT): C[m][n] = sum_k A[m][k] * W[n][k] (+ bias[n])
// A: [M,K] row-major, W: [N,K] row-major.  128x128x8 tiles, 8x8 per thread.
// ---------------------------------------------------------------------------
#define BM 128
#define BN 128
#define BK 8
#define TM 8
#define TN 8

__global__ __launch_bounds__(256)
void sgemm_nt(const float* __restrict__ A, const float* __restrict__ W,
              const float* __restrict__ bias, float* __restrict__ C,
              int M, int N, int K)
{
    __shared__ float As[BK][BM];
    __shared__ float Bs[BK][BN];

    const int tid = threadIdx.x;
    const int m0 = blockIdx.y * BM;
    const int n0 = blockIdx.x * BN;
    const int tr = (tid / 16) * TM;
    const int tc = (tid % 16) * TN;

    // global load mapping: each thread loads one float4 of A and one of W
    const int lr = tid >> 1;          // 0..127 (tile row)
    const int lk = (tid & 1) << 2;    // 0 or 4 (k offset)

    float acc[TM][TN];
#pragma unroll
    for (int i = 0; i < TM; i++)
#pragma unroll
        for (int j = 0; j < TN; j++) acc[i][j] = 0.0f;

    for (int k0 = 0; k0 < K; k0 += BK) {
        float4 a = *(const float4*)&A[(m0 + lr) * K + k0 + lk];
        float4 b = *(const float4*)&W[(n0 + lr) * K + k0 + lk];
        __syncthreads();
        As[lk + 0][lr] = a.x; As[lk + 1][lr] = a.y;
        As[lk + 2][lr] = a.z; As[lk + 3][lr] = a.w;
        Bs[lk + 0][lr] = b.x; Bs[lk + 1][lr] = b.y;
        Bs[lk + 2][lr] = b.z; Bs[lk + 3][lr] = b.w;
        __syncthreads();

#pragma unroll
        for (int k = 0; k < BK; k++) {
            float ra[TM], rb[TN];
            *(float4*)&ra[0] = *(const float4*)&As[k][tr];
            *(float4*)&ra[4] = *(const float4*)&As[k][tr + 4];
            *(float4*)&rb[0] = *(const float4*)&Bs[k][tc];
            *(float4*)&rb[4] = *(const float4*)&Bs[k][tc + 4];
#pragma unroll
            for (int i = 0; i < TM; i++)
#pragma unroll
                for (int j = 0; j < TN; j++)
                    acc[i][j] = fmaf(ra[i], rb[j], acc[i][j]);
        }
    }

    // epilogue
    float bval[TN];
#pragma unroll
    for (int j = 0; j < TN; j++) bval[j] = bias ? bias[n0 + tc + j] : 0.0f;

#pragma unroll
    for (int i = 0; i < TM; i++) {
        float4 o0, o1;
        o0.x = acc[i][0] + bval[0]; o0.y = acc[i][1] + bval[1];
        o0.z = acc[i][2] + bval[2]; o0.w = acc[i][3] + bval[3];
        o1.x = acc[i][4] + bval[4]; o1.y = acc[i][5] + bval[5];
        o1.z = acc[i][6] + bval[6]; o1.w = acc[i][7] + bval[7];
        *(float4*)&C[(m0 + tr + i) * N + n0 + tc]     = o0;
        *(float4*)&C[(m0 + tr + i) * N + n0 + tc + 4] = o1;
    }
}

// ---------------------------------------------------------------------------
// Flash-style attention: per block: one (batch, head, 64-query tile).
// 256 threads as 16x16; each thread owns a 4x4 micro-tile.
// Online softmax across 64-key tiles. dk = 64.
// Shared: Qs/Ks/Vs/Ps, each 64 x 65 (pad 1 to break bank conflicts).
// ---------------------------------------------------------------------------
#define ATS 64
#define APAD 65

__global__ __launch_bounds__(256)
void attn64(const float* __restrict__ Q, const float* __restrict__ Kt,
            const float* __restrict__ V, float* __restrict__ O)
{
    extern __shared__ float sm[];
    float* Qs = sm;                  // 64*65
    float* Ks = Qs + ATS * APAD;
    float* Vs = Ks + ATS * APAD;
    float* Ps = Vs + ATS * APAD;

    const int tid = threadIdx.x;
    const int ty = tid >> 4;         // 0..15 -> query rows
    const int tx = tid & 15;         // 0..15 -> key cols / dims
    const int b = blockIdx.z;
    const int h = blockIdx.y;
    const int q0 = blockIdx.x * ATS;
    const float scale = 0.125f;      // 1/sqrt(64)

    const int base = (b * SEQ) * DMODEL + h * DK;

    // Load Q tile (pre-scaled)
    for (int i = tid; i < ATS * (DK / 4); i += 256) {
        int r = i >> 4;
        int c = (i & 15) << 2;
        float4 v = *(const float4*)&Q[base + (q0 + r) * DMODEL + c];
        Qs[r * APAD + c + 0] = v.x * scale;
        Qs[r * APAD + c + 1] = v.y * scale;
        Qs[r * APAD + c + 2] = v.z * scale;
        Qs[r * APAD + c + 3] = v.w * scale;
    }

    float m_run[4], l_run[4], acc[4][4];
#pragma unroll
    for (int i = 0; i < 4; i++) {
        m_run[i] = -CUDART_INF_F;
        l_run[i] = 0.0f;
#pragma unroll
        for (int j = 0; j < 4; j++) acc[i][j] = 0.0f;
    }

    for (int kt = 0; kt < SEQ; kt += ATS) {
        __syncthreads();   // protect Ks/Vs/Ps from previous iteration (and Q load on iter 0)
        for (int i = tid; i < ATS * (DK / 4); i += 256) {
            int r = i >> 4;
            int c = (i & 15) << 2;
            float4 kv = *(const float4*)&Kt[base + (kt + r) * DMODEL + c];
            float4 vv = *(const float4*)&V [base + (kt + r) * DMODEL + c];
            Ks[r * APAD + c + 0] = kv.x; Ks[r * APAD + c + 1] = kv.y;
            Ks[r * APAD + c + 2] = kv.z; Ks[r * APAD + c + 3] = kv.w;
            Vs[r * APAD + c + 0] = vv.x; Vs[r * APAD + c + 1] = vv.y;
            Vs[r * APAD + c + 2] = vv.z; Vs[r * APAD + c + 3] = vv.w;
        }
        __syncthreads();

        // scores: s[i][j] = Qrow(4ty+i) . Krow(4tx+j)   (Q pre-scaled)
        float s[4][4];
#pragma unroll
        for (int i = 0; i < 4; i++)
#pragma unroll
            for (int j = 0; j < 4; j++) s[i][j] = 0.0f;

#pragma unroll 4
        for (int d = 0; d < DK; d++) {
            float qa[4], kb[4];
#pragma unroll
            for (int i = 0; i < 4; i++) qa[i] = Qs[(4 * ty + i) * APAD + d];
#pragma unroll
            for (int j = 0; j < 4; j++) kb[j] = Ks[(4 * tx + j) * APAD + d];
#pragma unroll
            for (int i = 0; i < 4; i++)
#pragma unroll
                for (int j = 0; j < 4; j++)
                    s[i][j] = fmaf(qa[i], kb[j], s[i][j]);
        }

        // online softmax update (per query row; reduce across the 16 tx lanes)
#pragma unroll
        for (int i = 0; i < 4; i++) {
            float mx = fmaxf(fmaxf(s[i][0], s[i][1]), fmaxf(s[i][2], s[i][3]));
#pragma unroll
            for (int o = 8; o >= 1; o >>= 1)
                mx = fmaxf(mx, __shfl_xor_sync(0xffffffffu, mx, o, 16));
            float nm = fmaxf(m_run[i], mx);
            float corr = __expf(m_run[i] - nm);
            float rs = 0.0f;
#pragma unroll
            for (int j = 0; j < 4; j++) {
                float p = __expf(s[i][j] - nm);
                s[i][j] = p;
                rs += p;
            }
#pragma unroll
            for (int o = 8; o >= 1; o >>= 1)
                rs += __shfl_xor_sync(0xffffffffu, rs, o, 16);
            l_run[i] = l_run[i] * corr + rs;
            m_run[i] = nm;
#pragma unroll
            for (int j = 0; j < 4; j++) acc[i][j] *= corr;
        }

        // stage P through shared
#pragma unroll
        for (int i = 0; i < 4; i++)
#pragma unroll
            for (int j = 0; j < 4; j++)
                Ps[(4 * ty + i) * APAD + 4 * tx + j] = s[i][j];
        __syncthreads();

        // acc += P * V  (64-deep)
#pragma unroll 4
        for (int kk = 0; kk < ATS; kk++) {
            float pv[4], vv[4];
#pragma unroll
            for (int i = 0; i < 4; i++) pv[i] = Ps[(4 * ty + i) * APAD + kk];
#pragma unroll
            for (int j = 0; j < 4; j++) vv[j] = Vs[kk * APAD + 4 * tx + j];
#pragma unroll
            for (int i = 0; i < 4; i++)
#pragma unroll
                for (int j = 0; j < 4; j++)
                    acc[i][j] = fmaf(pv[i], vv[j], acc[i][j]);
        }
    }

    // normalize and write ctx in [B,S,H*dk] layout
#pragma unroll
    for (int i = 0; i < 4; i++) {
        float inv = 1.0f / l_run[i];
#pragma unroll
        for (int j = 0; j < 4; j++)
            O[base + (q0 + 4 * ty + i) * DMODEL + 4 * tx + j] = acc[i][j] * inv;
    }
}

// ---------------------------------------------------------------------------
// Launch
// ---------------------------------------------------------------------------
extern "C" void kernel_launch(void* const* d_in, const int* in_sizes, int n_in,
                              void* d_out, int out_size)
{
    const float* query = (const float*)d_in[0];
    const float* key_  = (const float*)d_in[1];
    const float* value = (const float*)d_in[2];
    const float* w_q   = (const float*)d_in[3];
    const float* w_k   = (const float*)d_in[4];
    const float* w_v   = (const float*)d_in[5];
    const float* w_o   = (const float*)d_in[6];
    const float* b_o   = (const float*)d_in[7];
    float* out = (float*)d_out;

    float *pQ, *pK, *pV, *pC;
    cudaGetSymbolAddress((void**)&pQ, g_Q);
    cudaGetSymbolAddress((void**)&pK, g_K);
    cudaGetSymbolAddress((void**)&pV, g_V);
    cudaGetSymbolAddress((void**)&pC, g_C);

    dim3 gg(DMODEL / BN, MROWS / BM);  // (8, 64)
    sgemm_nt<<<gg, 256>>>(query, w_q, nullptr, pQ, MROWS, DMODEL, DMODEL);
    sgemm_nt<<<gg, 256>>>(key_,  w_k, nullptr, pK, MROWS, DMODEL, DMODEL);
    sgemm_nt<<<gg, 256>>>(value, w_v, nullptr, pV, MROWS, DMODEL, DMODEL);

    int smem = 4 * ATS * APAD * (int)sizeof(float);  // ~66.5 KB
    cudaFuncSetAttribute(attn64, cudaFuncAttributeMaxDynamicSharedMemorySize, smem);
    attn64<<<dim3(SEQ / ATS, NHEAD, BATCH), 256, smem>>>(pQ, pK, pV, pC);

    sgemm_nt<<<gg, 256>>>(pC, w_o, b_o, out, MROWS, DMODEL, DMODEL);
}

// round 2
// speedup vs baseline: 3.3505x; 3.3505x over previous
#include <cuda_runtime.h>
#include <cuda_bf16.h>
#include <math_constants.h>

// Problem constants
#define BATCH 4
#define SEQ   2048
#define DMODEL 1024
#define NHEAD 16
#define DK    64
#define MROWS (BATCH * SEQ)   // 8192

// ---------------------------------------------------------------------------
// Scratch (static __device__ arrays; no allocations allowed)
// ---------------------------------------------------------------------------
__device__ float g_Q[MROWS * DMODEL];
__device__ float g_K[MROWS * DMODEL];
__device__ float g_V[MROWS * DMODEL];
__device__ float g_C[MROWS * DMODEL];

// ---------------------------------------------------------------------------
// Helpers
// ---------------------------------------------------------------------------
__device__ __forceinline__ unsigned f2tf32(float x) {
    unsigned r;
    asm("cvt.rna.tf32.f32 %0, %1;" : "=r"(r) : "f"(x));
    return r;
}

__device__ __forceinline__ void mma_tf32(float* c, const unsigned* a, const unsigned* b) {
    asm volatile(
        "mma.sync.aligned.m16n8k8.row.col.f32.tf32.tf32.f32 "
        "{%0,%1,%2,%3}, {%4,%5,%6,%7}, {%8,%9}, {%0,%1,%2,%3};\n"
        : "+f"(c[0]), "+f"(c[1]), "+f"(c[2]), "+f"(c[3])
        : "r"(a[0]), "r"(a[1]), "r"(a[2]), "r"(a[3]), "r"(b[0]), "r"(b[1]));
}

// ---------------------------------------------------------------------------
// TF32 GEMM (NT): C[m][n] = sum_k A[m][k] * W[n][k] (+ bias[n])
// A: [M,K] row-major, W: [N,K] row-major.
// Tiles: BM=128, BN=64, BK=32. 256 threads = 8 warps (4x2), warp tile 32x64?
// -> warp tile 32(m) x 32(n): 2 m16 tiles x 4 n8 tiles.
// ---------------------------------------------------------------------------
#define GBM 128
#define GBN 64
#define GBK 32
#define GSTRIDE 36   // (GBK+4): %32 == 4 -> bank = 4*m + k, conflict-free for quads

__global__ __launch_bounds__(256)
void gemm_tf32(const float* __restrict__ A, const float* __restrict__ W,
               const float* __restrict__ bias, float* __restrict__ C,
               int M, int N, int K)
{
    __shared__ unsigned As[GBM * GSTRIDE];
    __shared__ unsigned Bs[GBN * GSTRIDE];

    const int tid  = threadIdx.x;
    const int lane = tid & 31;
    const int wrp  = tid >> 5;
    const int wm   = wrp >> 1;   // 0..3 -> row offset wm*32
    const int wn   = wrp & 1;    // 0..1 -> col offset wn*32
    const int rA   = lane >> 2;  // quad group
    const int cA   = lane & 3;   // thread in group

    const int ldrow = tid >> 3;        // 0..31
    const int ldcol = (tid & 7) << 2;  // 0,4,...,28

    const float* Ap = A + (size_t)(blockIdx.y * GBM) * K;
    const float* Wp = W + (size_t)(blockIdx.x * GBN) * K;

    float4 ar[4], br[2];
#pragma unroll
    for (int i = 0; i < 4; i++)
        ar[i] = *(const float4*)(Ap + (ldrow + i * 32) * K + ldcol);
#pragma unroll
    for (int i = 0; i < 2; i++)
        br[i] = *(const float4*)(Wp + (ldrow + i * 32) * K + ldcol);

    float c[2][4][4];
#pragma unroll
    for (int mt = 0; mt < 2; mt++)
#pragma unroll
        for (int nt = 0; nt < 4; nt++)
#pragma unroll
            for (int r = 0; r < 4; r++) c[mt][nt][r] = 0.0f;

    for (int k0 = 0; k0 < K; k0 += GBK) {
        __syncthreads();
#pragma unroll
        for (int i = 0; i < 4; i++) {
            unsigned* p = &As[(ldrow + i * 32) * GSTRIDE + ldcol];
            p[0] = f2tf32(ar[i].x); p[1] = f2tf32(ar[i].y);
            p[2] = f2tf32(ar[i].z); p[3] = f2tf32(ar[i].w);
        }
#pragma unroll
        for (int i = 0; i < 2; i++) {
            unsigned* p = &Bs[(ldrow + i * 32) * GSTRIDE + ldcol];
            p[0] = f2tf32(br[i].x); p[1] = f2tf32(br[i].y);
            p[2] = f2tf32(br[i].z); p[3] = f2tf32(br[i].w);
        }
        __syncthreads();

        if (k0 + GBK < K) {
#pragma unroll
            for (int i = 0; i < 4; i++)
                ar[i] = *(const float4*)(Ap + (ldrow + i * 32) * K + k0 + GBK + ldcol);
#pragma unroll
            for (int i = 0; i < 2; i++)
                br[i] = *(const float4*)(Wp + (ldrow + i * 32) * K + k0 + GBK + ldcol);
        }

#pragma unroll
        for (int kk = 0; kk < GBK; kk += 8) {
            unsigned af[2][4], bf[4][2];
#pragma unroll
            for (int mt = 0; mt < 2; mt++) {
                int row = wm * 32 + mt * 16;
                af[mt][0] = As[(row + rA) * GSTRIDE + kk + cA];
                af[mt][1] = As[(row + 8 + rA) * GSTRIDE + kk + cA];
                af[mt][2] = As[(row + rA) * GSTRIDE + kk + 4 + cA];
                af[mt][3] = As[(row + 8 + rA) * GSTRIDE + kk + 4 + cA];
            }
#pragma unroll
            for (int nt = 0; nt < 4; nt++) {
                int coln = wn * 32 + nt * 8 + rA;
                bf[nt][0] = Bs[coln * GSTRIDE + kk + cA];
                bf[nt][1] = Bs[coln * GSTRIDE + kk + 4 + cA];
            }
#pragma unroll
            for (int mt = 0; mt < 2; mt++)
#pragma unroll
                for (int nt = 0; nt < 4; nt++)
                    mma_tf32(c[mt][nt], af[mt], bf[nt]);
        }
    }

    // epilogue
#pragma unroll
    for (int mt = 0; mt < 2; mt++) {
        int row = blockIdx.y * GBM + wm * 32 + mt * 16 + rA;
#pragma unroll
        for (int nt = 0; nt < 4; nt++) {
            int col = blockIdx.x * GBN + wn * 32 + nt * 8 + 2 * cA;
            float bv0 = bias ? bias[col]     : 0.0f;
            float bv1 = bias ? bias[col + 1] : 0.0f;
            C[(size_t)row * N + col]           = c[mt][nt][0] + bv0;
            C[(size_t)row * N + col + 1]       = c[mt][nt][1] + bv1;
            C[(size_t)(row + 8) * N + col]     = c[mt][nt][2] + bv0;
            C[(size_t)(row + 8) * N + col + 1] = c[mt][nt][3] + bv1;
        }
    }
}

// ---------------------------------------------------------------------------
// Flash attention with TF32 mma. Block: 128 threads (4 warps), 64 q rows
// (16 per warp). K-tiles of 64 keys, online softmax on C fragments,
// P staged through SMEM (tf32) for the PV mma.
// SMEM stride 68: bank = 4*row + col -> conflict-free quad access.
// ---------------------------------------------------------------------------
#define ASTRIDE 68

__global__ __launch_bounds__(128)
void attn_tc(const float* __restrict__ Q, const float* __restrict__ Kg_,
             const float* __restrict__ Vg_, float* __restrict__ O)
{
    extern __shared__ unsigned sm[];
    unsigned* Qs = sm;                     // [64][68]
    unsigned* Ks = Qs + 64 * ASTRIDE;
    unsigned* Vs = Ks + 64 * ASTRIDE;
    unsigned* Ps = Vs + 64 * ASTRIDE;

    const int tid  = threadIdx.x;
    const int lane = tid & 31;
    const int wrp  = tid >> 5;       // 0..3 -> q rows wrp*16
    const int rA   = lane >> 2;
    const int cA   = lane & 3;
    const int b  = blockIdx.z;
    const int h  = blockIdx.y;
    const int q0 = blockIdx.x * 64;
    const float scale = 0.125f;      // 1/sqrt(64)

    const float* Qg = Q   + (size_t)(b * SEQ + q0) * DMODEL + h * DK;
    const float* Kp = Kg_ + (size_t)(b * SEQ) * DMODEL + h * DK;
    const float* Vp = Vg_ + (size_t)(b * SEQ) * DMODEL + h * DK;

    // Load Q tile (64x64), pre-scaled, tf32
    {
        int r0 = tid >> 4;              // 0..7
        int c0 = (tid & 15) << 2;       // 0..60
#pragma unroll
        for (int i = 0; i < 8; i++) {
            int r = r0 + i * 8;
            float4 v = *(const float4*)(Qg + (size_t)r * DMODEL + c0);
            unsigned* p = &Qs[r * ASTRIDE + c0];
            p[0] = f2tf32(v.x * scale); p[1] = f2tf32(v.y * scale);
            p[2] = f2tf32(v.z * scale); p[3] = f2tf32(v.w * scale);
        }
    }
    __syncthreads();

    // Hoist Q fragments (this warp's 16 rows, all 64 dims -> 8 ksteps)
    unsigned qf[8][4];
#pragma unroll
    for (int kk = 0; kk < 8; kk++) {
        qf[kk][0] = Qs[(wrp * 16 + rA) * ASTRIDE + kk * 8 + cA];
        qf[kk][1] = Qs[(wrp * 16 + 8 + rA) * ASTRIDE + kk * 8 + cA];
        qf[kk][2] = Qs[(wrp * 16 + rA) * ASTRIDE + kk * 8 + 4 + cA];
        qf[kk][3] = Qs[(wrp * 16 + 8 + rA) * ASTRIDE + kk * 8 + 4 + cA];
    }

    float of[8][4];
#pragma unroll
    for (int nt = 0; nt < 8; nt++)
#pragma unroll
        for (int r = 0; r < 4; r++) of[nt][r] = 0.0f;
    float m0 = -CUDART_INF_F, m1 = -CUDART_INF_F, l0 = 0.0f, l1 = 0.0f;

    for (int kt = 0; kt < SEQ; kt += 64) {
        __syncthreads();
        {
            int r0 = tid >> 4;
            int c0 = (tid & 15) << 2;
#pragma unroll
            for (int i = 0; i < 8; i++) {
                int r = r0 + i * 8;
                float4 kv = *(const float4*)(Kp + (size_t)(kt + r) * DMODEL + c0);
                float4 vv = *(const float4*)(Vp + (size_t)(kt + r) * DMODEL + c0);
                unsigned* pk = &Ks[r * ASTRIDE + c0];
                unsigned* pv = &Vs[r * ASTRIDE + c0];
                pk[0] = f2tf32(kv.x); pk[1] = f2tf32(kv.y);
                pk[2] = f2tf32(kv.z); pk[3] = f2tf32(kv.w);
                pv[0] = f2tf32(vv.x); pv[1] = f2tf32(vv.y);
                pv[2] = f2tf32(vv.z); pv[3] = f2tf32(vv.w);
            }
        }
        __syncthreads();

        // S = Q @ K^T : per warp 16 x 64 scores
        float sc[8][4];
#pragma unroll
        for (int nt = 0; nt < 8; nt++) {
#pragma unroll
            for (int r = 0; r < 4; r++) sc[nt][r] = 0.0f;
#pragma unroll
            for (int kk = 0; kk < 8; kk++) {
                unsigned bf[2];
                bf[0] = Ks[(nt * 8 + rA) * ASTRIDE + kk * 8 + cA];
                bf[1] = Ks[(nt * 8 + rA) * ASTRIDE + kk * 8 + 4 + cA];
                mma_tf32(sc[nt], qf[kk], bf);
            }
        }

        // online softmax (rows r=rA and rA+8 of this warp's 16)
        float mx0 = -CUDART_INF_F, mx1 = -CUDART_INF_F;
#pragma unroll
        for (int nt = 0; nt < 8; nt++) {
            mx0 = fmaxf(mx0, fmaxf(sc[nt][0], sc[nt][1]));
            mx1 = fmaxf(mx1, fmaxf(sc[nt][2], sc[nt][3]));
        }
        mx0 = fmaxf(mx0, __shfl_xor_sync(0xffffffffu, mx0, 1));
        mx0 = fmaxf(mx0, __shfl_xor_sync(0xffffffffu, mx0, 2));
        mx1 = fmaxf(mx1, __shfl_xor_sync(0xffffffffu, mx1, 1));
        mx1 = fmaxf(mx1, __shfl_xor_sync(0xffffffffu, mx1, 2));

        float nm0 = fmaxf(m0, mx0), nm1 = fmaxf(m1, mx1);
        float corr0 = __expf(m0 - nm0), corr1 = __expf(m1 - nm1);
        float s0 = 0.0f, s1 = 0.0f;
#pragma unroll
        for (int nt = 0; nt < 8; nt++) {
            float p0 = __expf(sc[nt][0] - nm0);
            float p1 = __expf(sc[nt][1] - nm0);
            float p2 = __expf(sc[nt][2] - nm1);
            float p3 = __expf(sc[nt][3] - nm1);
            s0 += p0 + p1; s1 += p2 + p3;
            int col = nt * 8 + 2 * cA;
            Ps[(wrp * 16 + rA) * ASTRIDE + col]     = f2tf32(p0);
            Ps[(wrp * 16 + rA) * ASTRIDE + col + 1] = f2tf32(p1);
            Ps[(wrp * 16 + 8 + rA) * ASTRIDE + col]     = f2tf32(p2);
            Ps[(wrp * 16 + 8 + rA) * ASTRIDE + col + 1] = f2tf32(p3);
        }
        s0 += __shfl_xor_sync(0xffffffffu, s0, 1);
        s0 += __shfl_xor_sync(0xffffffffu, s0, 2);
        s1 += __shfl_xor_sync(0xffffffffu, s1, 1);
        s1 += __shfl_xor_sync(0xffffffffu, s1, 2);
        l0 = l0 * corr0 + s0;
        l1 = l1 * corr1 + s1;
        m0 = nm0; m1 = nm1;
#pragma unroll
        for (int nt = 0; nt < 8; nt++) {
            of[nt][0] *= corr0; of[nt][1] *= corr0;
            of[nt][2] *= corr1; of[nt][3] *= corr1;
        }
        __syncwarp();

        // O += P @ V : m=16 q, n=64 dims, k=64 keys
#pragma unroll
        for (int kk = 0; kk < 8; kk++) {
            unsigned af[4];
            af[0] = Ps[(wrp * 16 + rA) * ASTRIDE + kk * 8 + cA];
            af[1] = Ps[(wrp * 16 + 8 + rA) * ASTRIDE + kk * 8 + cA];
            af[2] = Ps[(wrp * 16 + rA) * ASTRIDE + kk * 8 + 4 + cA];
            af[3] = Ps[(wrp * 16 + 8 + rA) * ASTRIDE + kk * 8 + 4 + cA];
#pragma unroll
            for (int nt = 0; nt < 8; nt++) {
                unsigned bf[2];
                bf[0] = Vs[(kk * 8 + cA) * ASTRIDE + nt * 8 + rA];
                bf[1] = Vs[(kk * 8 + 4 + cA) * ASTRIDE + nt * 8 + rA];
                mma_tf32(of[nt], af, bf);
            }
        }
    }

    // normalize and write ctx in [B,S,H*dk] layout
    float inv0 = 1.0f / l0, inv1 = 1.0f / l1;
    float* Op = O + (size_t)(b * SEQ + q0 + wrp * 16) * DMODEL + h * DK;
#pragma unroll
    for (int nt = 0; nt < 8; nt++) {
        int col = nt * 8 + 2 * cA;
        Op[(size_t)rA * DMODEL + col]           = of[nt][0] * inv0;
        Op[(size_t)rA * DMODEL + col + 1]       = of[nt][1] * inv0;
        Op[(size_t)(rA + 8) * DMODEL + col]     = of[nt][2] * inv1;
        Op[(size_t)(rA + 8) * DMODEL + col + 1] = of[nt][3] * inv1;
    }
}

// ---------------------------------------------------------------------------
// Launch
// ---------------------------------------------------------------------------
extern "C" void kernel_launch(void* const* d_in, const int* in_sizes, int n_in,
                              void* d_out, int out_size)
{
    const float* query = (const float*)d_in[0];
    const float* key_  = (const float*)d_in[1];
    const float* value = (const float*)d_in[2];
    const float* w_q   = (const float*)d_in[3];
    const float* w_k   = (const float*)d_in[4];
    const float* w_v   = (const float*)d_in[5];
    const float* w_o   = (const float*)d_in[6];
    const float* b_o   = (const float*)d_in[7];
    float* out = (float*)d_out;

    float *pQ, *pK, *pV, *pC;
    cudaGetSymbolAddress((void**)&pQ, g_Q);
    cudaGetSymbolAddress((void**)&pK, g_K);
    cudaGetSymbolAddress((void**)&pV, g_V);
    cudaGetSymbolAddress((void**)&pC, g_C);

    dim3 gg(DMODEL / GBN, MROWS / GBM);  // (16, 64)
    gemm_tf32<<<gg, 256>>>(query, w_q, nullptr, pQ, MROWS, DMODEL, DMODEL);
    gemm_tf32<<<gg, 256>>>(key_,  w_k, nullptr, pK, MROWS, DMODEL, DMODEL);
    gemm_tf32<<<gg, 256>>>(value, w_v, nullptr, pV, MROWS, DMODEL, DMODEL);

    int smem = 4 * 64 * ASTRIDE * (int)sizeof(unsigned);  // ~69.6 KB
    cudaFuncSetAttribute(attn_tc, cudaFuncAttributeMaxDynamicSharedMemorySize, smem);
    attn_tc<<<dim3(SEQ / 64, NHEAD, BATCH), 128, smem>>>(pQ, pK, pV, pC);

    gemm_tf32<<<gg, 256>>>(pC, w_o, b_o, out, MROWS, DMODEL, DMODEL);
}

// round 4
// speedup vs baseline: 5.1177x; 1.5274x over previous
#include <cuda_runtime.h>
#include <cuda_fp16.h>
#include <math_constants.h>
#include <cstdint>

// Problem constants
#define BATCH 4
#define SEQ   2048
#define DMODEL 1024
#define NHEAD 16
#define DK    64
#define MROWS (BATCH * SEQ)   // 8192

// ---------------------------------------------------------------------------
// Scratch (static __device__ arrays; no allocations allowed)
// ---------------------------------------------------------------------------
__device__ float g_Q[MROWS * DMODEL];
__device__ float g_K[MROWS * DMODEL];
__device__ float g_V[MROWS * DMODEL];
__device__ float g_C[MROWS * DMODEL];

// ---------------------------------------------------------------------------
// Helpers
// ---------------------------------------------------------------------------
__device__ __forceinline__ uint32_t smem_u32(const void* p) {
    uint32_t a;
    asm("{ .reg .u64 t; cvta.to.shared.u64 t, %1; cvt.u32.u64 %0, t; }" : "=r"(a) : "l"(p));
    return a;
}

__device__ __forceinline__ uint32_t pack_half2(float a, float b) {
    __half2 h = __floats2half2_rn(a, b);
    return *reinterpret_cast<uint32_t*>(&h);
}

__device__ __forceinline__ void ldsm4(uint32_t* r, uint32_t addr) {
    asm volatile("ldmatrix.sync.aligned.m8n8.x4.shared.b16 {%0,%1,%2,%3}, [%4];"
                 : "=r"(r[0]), "=r"(r[1]), "=r"(r[2]), "=r"(r[3]) : "r"(addr));
}
__device__ __forceinline__ void ldsm2(uint32_t* r, uint32_t addr) {
    asm volatile("ldmatrix.sync.aligned.m8n8.x2.shared.b16 {%0,%1}, [%2];"
                 : "=r"(r[0]), "=r"(r[1]) : "r"(addr));
}
__device__ __forceinline__ void ldsm2t(uint32_t* r, uint32_t addr) {
    asm volatile("ldmatrix.sync.aligned.m8n8.x2.trans.shared.b16 {%0,%1}, [%2];"
                 : "=r"(r[0]), "=r"(r[1]) : "r"(addr));
}

__device__ __forceinline__ void mma16816(float* c, const uint32_t* a, const uint32_t* b) {
    asm volatile(
        "mma.sync.aligned.m16n8k16.row.col.f32.f16.f16.f32 "
        "{%0,%1,%2,%3}, {%4,%5,%6,%7}, {%8,%9}, {%0,%1,%2,%3};"
        : "+f"(c[0]), "+f"(c[1]), "+f"(c[2]), "+f"(c[3])
        : "r"(a[0]), "r"(a[1]), "r"(a[2]), "r"(a[3]), "r"(b[0]), "r"(b[1]));
}

// ---------------------------------------------------------------------------
// FP16 GEMM (NT): C[m][n] = sum_k A[m][k]*W[n][k] (+bias[n])
// BM=128, BN=128, BK=32, 256 threads = 8 warps (2x4), warp tile 64x32.
// Double-buffered SMEM; fragments via ldmatrix.
// ---------------------------------------------------------------------------
#define BM 128
#define BN 128
#define BK 32
#define KST 40   // half-unit row stride (80B): ldmatrix conflict-free

__global__ __launch_bounds__(256)
void gemm_f16(const float* __restrict__ A, const float* __restrict__ W,
              const float* __restrict__ bias, float* __restrict__ C,
              int M, int N, int K)
{
    __shared__ __half As[2][BM * KST];
    __shared__ __half Bs[2][BM * KST];

    const int tid  = threadIdx.x;
    const int lane = tid & 31;
    const int wid  = tid >> 5;
    const int wm   = wid >> 2;   // 0..1 -> rows wm*64
    const int wn   = wid & 3;    // 0..3 -> cols wn*32

    const float* Ap = A + (size_t)(blockIdx.y * BM) * K;
    const float* Wp = W + (size_t)(blockIdx.x * BN) * K;

    float acc[4][4][4];
#pragma unroll
    for (int mt = 0; mt < 4; mt++)
#pragma unroll
        for (int nt = 0; nt < 4; nt++)
#pragma unroll
            for (int r = 0; r < 4; r++) acc[mt][nt][r] = 0.0f;

    const int lr = tid >> 3;          // 0..31? no: 0..31 -> with i*256 covers 128 rows
    const int lc = (tid & 7) << 2;    // 0,4,...,28

    float4 pa[4], pb[4];
#pragma unroll
    for (int i = 0; i < 4; i++) {
        int r = lr + i * 32;
        pa[i] = *(const float4*)(Ap + (size_t)r * K + lc);
        pb[i] = *(const float4*)(Wp + (size_t)r * K + lc);
    }
#pragma unroll
    for (int i = 0; i < 4; i++) {
        int r = lr + i * 32;
        uint2 ah, bh;
        ah.x = pack_half2(pa[i].x, pa[i].y); ah.y = pack_half2(pa[i].z, pa[i].w);
        bh.x = pack_half2(pb[i].x, pb[i].y); bh.y = pack_half2(pb[i].z, pb[i].w);
        *(uint2*)&As[0][r * KST + lc] = ah;
        *(uint2*)&Bs[0][r * KST + lc] = bh;
    }
    __syncthreads();

    const int nslab = K / BK;  // 32
    for (int s = 0; s < nslab; s++) {
        const int buf = s & 1;
        if (s + 1 < nslab) {
            const int k0 = (s + 1) * BK;
#pragma unroll
            for (int i = 0; i < 4; i++) {
                int r = lr + i * 32;
                pa[i] = *(const float4*)(Ap + (size_t)r * K + k0 + lc);
                pb[i] = *(const float4*)(Wp + (size_t)r * K + k0 + lc);
            }
        }
        // compute on buf
#pragma unroll
        for (int ks = 0; ks < 2; ks++) {
            uint32_t af[4][4], bf[4][2];
#pragma unroll
            for (int mt = 0; mt < 4; mt++) {
                int row = wm * 64 + mt * 16 + (lane & 15);
                int col = ks * 16 + (lane >> 4) * 8;
                ldsm4(af[mt], smem_u32(&As[buf][row * KST + col]));
            }
#pragma unroll
            for (int nt = 0; nt < 4; nt++) {
                int row = wn * 32 + nt * 8 + (lane & 7);
                int col = ks * 16 + ((lane >> 3) & 1) * 8;
                ldsm2(bf[nt], smem_u32(&Bs[buf][row * KST + col]));
            }
#pragma unroll
            for (int mt = 0; mt < 4; mt++)
#pragma unroll
                for (int nt = 0; nt < 4; nt++)
                    mma16816(acc[mt][nt], af[mt], bf[nt]);
        }
        if (s + 1 < nslab) {
            __syncthreads();
            const int nb = buf ^ 1;
#pragma unroll
            for (int i = 0; i < 4; i++) {
                int r = lr + i * 32;
                uint2 ah, bh;
                ah.x = pack_half2(pa[i].x, pa[i].y); ah.y = pack_half2(pa[i].z, pa[i].w);
                bh.x = pack_half2(pb[i].x, pb[i].y); bh.y = pack_half2(pb[i].z, pb[i].w);
                *(uint2*)&As[nb][r * KST + lc] = ah;
                *(uint2*)&Bs[nb][r * KST + lc] = bh;
            }
            __syncthreads();
        }
    }

    // epilogue
    const int rA = lane >> 2, cA = lane & 3;
#pragma unroll
    for (int mt = 0; mt < 4; mt++) {
        int row = blockIdx.y * BM + wm * 64 + mt * 16 + rA;
#pragma unroll
        for (int nt = 0; nt < 4; nt++) {
            int col = blockIdx.x * BN + wn * 32 + nt * 8 + 2 * cA;
            float b0 = bias ? bias[col] : 0.0f;
            float b1 = bias ? bias[col + 1] : 0.0f;
            float2 v0 = { acc[mt][nt][0] + b0, acc[mt][nt][1] + b1 };
            float2 v1 = { acc[mt][nt][2] + b0, acc[mt][nt][3] + b1 };
            *(float2*)&C[(size_t)row * N + col]       = v0;
            *(float2*)&C[(size_t)(row + 8) * N + col] = v1;
        }
    }
}

// ---------------------------------------------------------------------------
// Flash attention, fp16 mma + ldmatrix. 256 threads = 8 warps.
// 128 q-rows per CTA (16 per warp), K/V tiles of 64 keys shared by all warps.
// Online softmax on C fragments; P staged as fp16; V via ldmatrix.trans.
// ---------------------------------------------------------------------------
#define AST 72   // half-unit stride (144B): ldmatrix conflict-free

__global__ __launch_bounds__(256)
void attn_f16(const float* __restrict__ Q, const float* __restrict__ Kg,
              const float* __restrict__ Vg, float* __restrict__ O)
{
    extern __shared__ __half sh[];
    __half* Qs = sh;                 // [128][72]
    __half* Ks = sh + 128 * AST;     // [64][72]
    __half* Vs = Ks + 64 * AST;      // [64][72]
    __half* Ps = Vs + 64 * AST;      // [128][72]

    const int tid  = threadIdx.x;
    const int lane = tid & 31;
    const int wrp  = tid >> 5;       // 0..7 -> q rows wrp*16
    const int rA   = lane >> 2;
    const int cA   = lane & 3;
    const int b  = blockIdx.z;
    const int h  = blockIdx.y;
    const int q0 = blockIdx.x * 128;
    const float scale = 0.125f;

    const float* Qg = Q  + (size_t)(b * SEQ + q0) * DMODEL + h * DK;
    const float* Kp = Kg + (size_t)(b * SEQ) * DMODEL + h * DK;
    const float* Vp = Vg + (size_t)(b * SEQ) * DMODEL + h * DK;

    // Load Q tile (128x64), pre-scaled, fp16
#pragma unroll
    for (int i = 0; i < 8; i++) {
        int id = tid + i * 256;
        int r = id >> 4, c = (id & 15) << 2;
        float4 v = *(const float4*)(Qg + (size_t)r * DMODEL + c);
        uint2 hv;
        hv.x = pack_half2(v.x * scale, v.y * scale);
        hv.y = pack_half2(v.z * scale, v.w * scale);
        *(uint2*)&Qs[r * AST + c] = hv;
    }
    __syncthreads();

    // Hoist Q fragments (16 rows x 64 dims -> 4 ksteps)
    uint32_t qf[4][4];
#pragma unroll
    for (int ks = 0; ks < 4; ks++) {
        int row = wrp * 16 + (lane & 15);
        int col = ks * 16 + (lane >> 4) * 8;
        ldsm4(qf[ks], smem_u32(&Qs[row * AST + col]));
    }

    float of[8][4];
#pragma unroll
    for (int nt = 0; nt < 8; nt++)
#pragma unroll
        for (int r = 0; r < 4; r++) of[nt][r] = 0.0f;
    float m0 = -CUDART_INF_F, m1 = -CUDART_INF_F, l0 = 0.0f, l1 = 0.0f;

    for (int kt = 0; kt < SEQ; kt += 64) {
        __syncthreads();
#pragma unroll
        for (int i = 0; i < 4; i++) {
            int id = tid + i * 256;
            int r = id >> 4, c = (id & 15) << 2;
            float4 kv = *(const float4*)(Kp + (size_t)(kt + r) * DMODEL + c);
            float4 vv = *(const float4*)(Vp + (size_t)(kt + r) * DMODEL + c);
            uint2 kh, vh;
            kh.x = pack_half2(kv.x, kv.y); kh.y = pack_half2(kv.z, kv.w);
            vh.x = pack_half2(vv.x, vv.y); vh.y = pack_half2(vv.z, vv.w);
            *(uint2*)&Ks[r * AST + c] = kh;
            *(uint2*)&Vs[r * AST + c] = vh;
        }
        __syncthreads();

        // S = Q @ K^T : 16 x 64 per warp
        float sc[8][4];
#pragma unroll
        for (int nt = 0; nt < 8; nt++)
#pragma unroll
            for (int r = 0; r < 4; r++) sc[nt][r] = 0.0f;
#pragma unroll
        for (int ks = 0; ks < 4; ks++) {
#pragma unroll
            for (int nt = 0; nt < 8; nt++) {
                uint32_t bf[2];
                int row = nt * 8 + (lane & 7);
                int col = ks * 16 + ((lane >> 3) & 1) * 8;
                ldsm2(bf, smem_u32(&Ks[row * AST + col]));
                mma16816(sc[nt], qf[ks], bf);
            }
        }

        // online softmax (rows rA and rA+8)
        float mx0 = -CUDART_INF_F, mx1 = -CUDART_INF_F;
#pragma unroll
        for (int nt = 0; nt < 8; nt++) {
            mx0 = fmaxf(mx0, fmaxf(sc[nt][0], sc[nt][1]));
            mx1 = fmaxf(mx1, fmaxf(sc[nt][2], sc[nt][3]));
        }
        mx0 = fmaxf(mx0, __shfl_xor_sync(0xffffffffu, mx0, 1));
        mx0 = fmaxf(mx0, __shfl_xor_sync(0xffffffffu, mx0, 2));
        mx1 = fmaxf(mx1, __shfl_xor_sync(0xffffffffu, mx1, 1));
        mx1 = fmaxf(mx1, __shfl_xor_sync(0xffffffffu, mx1, 2));

        float nm0 = fmaxf(m0, mx0), nm1 = fmaxf(m1, mx1);
        float corr0 = __expf(m0 - nm0), corr1 = __expf(m1 - nm1);
        float s0 = 0.0f, s1 = 0.0f;
#pragma unroll
        for (int nt = 0; nt < 8; nt++) {
            float p0 = __expf(sc[nt][0] - nm0);
            float p1 = __expf(sc[nt][1] - nm0);
            float p2 = __expf(sc[nt][2] - nm1);
            float p3 = __expf(sc[nt][3] - nm1);
            s0 += p0 + p1; s1 += p2 + p3;
            int col = nt * 8 + 2 * cA;
            *(uint32_t*)&Ps[(wrp * 16 + rA) * AST + col]     = pack_half2(p0, p1);
            *(uint32_t*)&Ps[(wrp * 16 + 8 + rA) * AST + col] = pack_half2(p2, p3);
        }
        s0 += __shfl_xor_sync(0xffffffffu, s0, 1);
        s0 += __shfl_xor_sync(0xffffffffu, s0, 2);
        s1 += __shfl_xor_sync(0xffffffffu, s1, 1);
        s1 += __shfl_xor_sync(0xffffffffu, s1, 2);
        l0 = l0 * corr0 + s0;
        l1 = l1 * corr1 + s1;
        m0 = nm0; m1 = nm1;
#pragma unroll
        for (int nt = 0; nt < 8; nt++) {
            of[nt][0] *= corr0; of[nt][1] *= corr0;
            of[nt][2] *= corr1; of[nt][3] *= corr1;
        }
        __syncwarp();

        // O += P @ V : A = P (16x64 keys), B = V^T via ldmatrix.trans
#pragma unroll
        for (int ks = 0; ks < 4; ks++) {
            uint32_t af[4];
            int prow = wrp * 16 + (lane & 15);
            int pcol = ks * 16 + (lane >> 4) * 8;
            ldsm4(af, smem_u32(&Ps[prow * AST + pcol]));
#pragma unroll
            for (int nt = 0; nt < 8; nt++) {
                uint32_t bf[2];
                int vrow = ks * 16 + (lane & 15);
                ldsm2t(bf, smem_u32(&Vs[vrow * AST + nt * 8]));
                mma16816(of[nt], af, bf);
            }
        }
    }

    // normalize and write ctx in [B,S,H*dk] layout
    float inv0 = 1.0f / l0, inv1 = 1.0f / l1;
    float* Op = O + (size_t)(b * SEQ + q0 + wrp * 16) * DMODEL + h * DK;
#pragma unroll
    for (int nt = 0; nt < 8; nt++) {
        int col = nt * 8 + 2 * cA;
        float2 v0 = { of[nt][0] * inv0, of[nt][1] * inv0 };
        float2 v1 = { of[nt][2] * inv1, of[nt][3] * inv1 };
        *(float2*)&Op[(size_t)rA * DMODEL + col]       = v0;
        *(float2*)&Op[(size_t)(rA + 8) * DMODEL + col] = v1;
    }
}

// ---------------------------------------------------------------------------
// Launch
// ---------------------------------------------------------------------------
extern "C" void kernel_launch(void* const* d_in, const int* in_sizes, int n_in,
                              void* d_out, int out_size)
{
    const float* query = (const float*)d_in[0];
    const float* key_  = (const float*)d_in[1];
    const float* value = (const float*)d_in[2];
    const float* w_q   = (const float*)d_in[3];
    const float* w_k   = (const float*)d_in[4];
    const float* w_v   = (const float*)d_in[5];
    const float* w_o   = (const float*)d_in[6];
    const float* b_o   = (const float*)d_in[7];
    float* out = (float*)d_out;

    float *pQ, *pK, *pV, *pC;
    cudaGetSymbolAddress((void**)&pQ, g_Q);
    cudaGetSymbolAddress((void**)&pK, g_K);
    cudaGetSymbolAddress((void**)&pV, g_V);
    cudaGetSymbolAddress((void**)&pC, g_C);

    dim3 gg(DMODEL / BN, MROWS / BM);  // (8, 64)
    gemm_f16<<<gg, 256>>>(query, w_q, nullptr, pQ, MROWS, DMODEL, DMODEL);
    gemm_f16<<<gg, 256>>>(key_,  w_k, nullptr, pK, MROWS, DMODEL, DMODEL);
    gemm_f16<<<gg, 256>>>(value, w_v, nullptr, pV, MROWS, DMODEL, DMODEL);

    int smem = (128 + 64 + 64 + 128) * AST * (int)sizeof(__half);  // 55,296B
    cudaFuncSetAttribute(attn_f16, cudaFuncAttributeMaxDynamicSharedMemorySize, smem);
    attn_f16<<<dim3(SEQ / 128, NHEAD, BATCH), 256, smem>>>(pQ, pK, pV, pC);

    gemm_f16<<<gg, 256>>>(pC, w_o, b_o, out, MROWS, DMODEL, DMODEL);
}

// round 7
// speedup vs baseline: 6.7183x; 1.3128x over previous
#include <cuda_runtime.h>
#include <cuda_fp16.h>
#include <math_constants.h>
#include <cstdint>

// Problem constants
#define BATCH 4
#define SEQ   2048
#define DMODEL 1024
#define NHEAD 16
#define DK    64
#define MROWS (BATCH * SEQ)   // 8192

// ---------------------------------------------------------------------------
// Scratch (static __device__ arrays; no allocations allowed)
// ---------------------------------------------------------------------------
__device__ __half g_qx[MROWS * DMODEL];    // fp16 inputs
__device__ __half g_kx[MROWS * DMODEL];
__device__ __half g_vx[MROWS * DMODEL];
__device__ __half g_wq[DMODEL * DMODEL];   // fp16 weights
__device__ __half g_wk[DMODEL * DMODEL];
__device__ __half g_wv[DMODEL * DMODEL];
__device__ __half g_wo[DMODEL * DMODEL];
__device__ __half g_Qh[MROWS * DMODEL];    // fp16 intermediates
__device__ __half g_Kh[MROWS * DMODEL];
__device__ __half g_Vh[MROWS * DMODEL];
__device__ __half g_Ch[MROWS * DMODEL];

// ---------------------------------------------------------------------------
// Helpers
// ---------------------------------------------------------------------------
__device__ __forceinline__ uint32_t smem_u32(const void* p) {
    uint32_t a;
    asm("{ .reg .u64 t; cvta.to.shared.u64 t, %1; cvt.u32.u64 %0, t; }" : "=r"(a) : "l"(p));
    return a;
}
__device__ __forceinline__ uint32_t pack_half2(float a, float b) {
    __half2 h = __floats2half2_rn(a, b);
    return *reinterpret_cast<uint32_t*>(&h);
}
__device__ __forceinline__ void cp16(uint32_t dst, const void* src) {
    asm volatile("cp.async.cg.shared.global [%0], [%1], 16;" :: "r"(dst), "l"(src));
}
#define CP_COMMIT() asm volatile("cp.async.commit_group;" ::: "memory")
#define CP_WAIT(n)  asm volatile("cp.async.wait_group %0;" :: "n"(n) : "memory")

__device__ __forceinline__ void ldsm4(uint32_t* r, uint32_t addr) {
    asm volatile("ldmatrix.sync.aligned.m8n8.x4.shared.b16 {%0,%1,%2,%3}, [%4];"
                 : "=r"(r[0]), "=r"(r[1]), "=r"(r[2]), "=r"(r[3]) : "r"(addr));
}
__device__ __forceinline__ void ldsm2(uint32_t* r, uint32_t addr) {
    asm volatile("ldmatrix.sync.aligned.m8n8.x2.shared.b16 {%0,%1}, [%2];"
                 : "=r"(r[0]), "=r"(r[1]) : "r"(addr));
}
__device__ __forceinline__ void ldsm2t(uint32_t* r, uint32_t addr) {
    asm volatile("ldmatrix.sync.aligned.m8n8.x2.trans.shared.b16 {%0,%1}, [%2];"
                 : "=r"(r[0]), "=r"(r[1]) : "r"(addr));
}
__device__ __forceinline__ void mma16816(float* c, const uint32_t* a, const uint32_t* b) {
    asm volatile(
        "mma.sync.aligned.m16n8k16.row.col.f32.f16.f16.f32 "
        "{%0,%1,%2,%3}, {%4,%5,%6,%7}, {%8,%9}, {%0,%1,%2,%3};"
        : "+f"(c[0]), "+f"(c[1]), "+f"(c[2]), "+f"(c[3])
        : "r"(a[0]), "r"(a[1]), "r"(a[2]), "r"(a[3]), "r"(b[0]), "r"(b[1]));
}

// ---------------------------------------------------------------------------
// fp32 -> fp16 conversion (one-shot)
// ---------------------------------------------------------------------------
__global__ __launch_bounds__(256)
void cvt16(const float* __restrict__ in, __half* __restrict__ out, int n4)
{
    int i = blockIdx.x * 256 + threadIdx.x;
    if (i < n4) {
        float4 v = *(const float4*)(in + (size_t)i * 4);
        uint2 h;
        h.x = pack_half2(v.x, v.y);
        h.y = pack_half2(v.z, v.w);
        *(uint2*)(out + (size_t)i * 4) = h;
    }
}

// ---------------------------------------------------------------------------
// FP16 GEMM (NT): C[m][n] = alpha * sum_k A[m][k]*W[n][k] (+bias[n])
// A fp16 [M,K], W fp16 [N,K]. BM=BN=128, BK=64. 256 thr = 8 warps (2x4),
// warp tile 64x32. cp.async double-buffered.
// ---------------------------------------------------------------------------
#define BM 128
#define BN 128
#define BK 64
#define KST 72   // half-unit row stride (144B)
#define GSM_BUF (BM * KST)                 // halves per tile buffer
#define GSM_TOTAL (4 * GSM_BUF * 2)        // bytes: As[2] + Bs[2]

template<bool F16OUT>
__global__ __launch_bounds__(256)
void gemm_f16(const __half* __restrict__ A, const __half* __restrict__ W,
              const float* __restrict__ bias, void* __restrict__ Cout,
              int M, int N, int K, float alpha)
{
    extern __shared__ __half sh[];
    __half* As[2] = { sh, sh + GSM_BUF };
    __half* Bs[2] = { sh + 2 * GSM_BUF, sh + 3 * GSM_BUF };

    const int tid  = threadIdx.x;
    const int lane = tid & 31;
    const int wid  = tid >> 5;
    const int wm   = wid >> 2;   // 0..1
    const int wn   = wid & 3;    // 0..3

    const __half* Ap = A + (size_t)(blockIdx.y * BM) * K;
    const __half* Wp = W + (size_t)(blockIdx.x * BN) * K;

    float acc[4][4][4];
#pragma unroll
    for (int mt = 0; mt < 4; mt++)
#pragma unroll
        for (int nt = 0; nt < 4; nt++)
#pragma unroll
            for (int r = 0; r < 4; r++) acc[mt][nt][r] = 0.0f;

    const int nslab = K / BK;  // 16
    auto load_tile = [&](int slab, int buf) {
        // 128 rows x 64 halves = 1024 16B-chunks per matrix; 4 per thread
#pragma unroll
        for (int i = 0; i < 4; i++) {
            int id = tid + i * 256;
            int r = id >> 3, c = (id & 7) << 3;   // halves
            cp16(smem_u32(&As[buf][r * KST + c]), Ap + (size_t)r * K + slab * BK + c);
        }
#pragma unroll
        for (int i = 0; i < 4; i++) {
            int id = tid + i * 256;
            int r = id >> 3, c = (id & 7) << 3;
            cp16(smem_u32(&Bs[buf][r * KST + c]), Wp + (size_t)r * K + slab * BK + c);
        }
        CP_COMMIT();
    };

    load_tile(0, 0);
    load_tile(1, 1);

    for (int s = 0; s < nslab; s++) {
        const int buf = s & 1;
        // pending: tiles s and (s+1 if present); ensure tile s landed
        if (s + 1 < nslab) CP_WAIT(1); else CP_WAIT(0);
        __syncthreads();

#pragma unroll
        for (int ks = 0; ks < 4; ks++) {
            uint32_t af[4][4], bf[4][2];
#pragma unroll
            for (int mt = 0; mt < 4; mt++) {
                int row = wm * 64 + mt * 16 + (lane & 15);
                int col = ks * 16 + (lane >> 4) * 8;
                ldsm4(af[mt], smem_u32(&As[buf][row * KST + col]));
            }
#pragma unroll
            for (int nt = 0; nt < 4; nt++) {
                int row = wn * 32 + nt * 8 + (lane & 7);
                int col = ks * 16 + ((lane >> 3) & 1) * 8;
                ldsm2(bf[nt], smem_u32(&Bs[buf][row * KST + col]));
            }
#pragma unroll
            for (int mt = 0; mt < 4; mt++)
#pragma unroll
                for (int nt = 0; nt < 4; nt++)
                    mma16816(acc[mt][nt], af[mt], bf[nt]);
        }
        __syncthreads();
        if (s + 2 < nslab) load_tile(s + 2, buf);
    }

    // epilogue
    const int rA = lane >> 2, cA = lane & 3;
#pragma unroll
    for (int mt = 0; mt < 4; mt++) {
        int row = blockIdx.y * BM + wm * 64 + mt * 16 + rA;
#pragma unroll
        for (int nt = 0; nt < 4; nt++) {
            int col = blockIdx.x * BN + wn * 32 + nt * 8 + 2 * cA;
            if (F16OUT) {
                __half* C = (__half*)Cout;
                *(uint32_t*)&C[(size_t)row * N + col] =
                    pack_half2(acc[mt][nt][0] * alpha, acc[mt][nt][1] * alpha);
                *(uint32_t*)&C[(size_t)(row + 8) * N + col] =
                    pack_half2(acc[mt][nt][2] * alpha, acc[mt][nt][3] * alpha);
            } else {
                float* C = (float*)Cout;
                float b0 = bias ? bias[col] : 0.0f;
                float b1 = bias ? bias[col + 1] : 0.0f;
                float2 v0 = { acc[mt][nt][0] + b0, acc[mt][nt][1] + b1 };
                float2 v1 = { acc[mt][nt][2] + b0, acc[mt][nt][3] + b1 };
                *(float2*)&C[(size_t)row * N + col]       = v0;
                *(float2*)&C[(size_t)(row + 8) * N + col] = v1;
            }
        }
    }
}

// ---------------------------------------------------------------------------
// Flash attention, fp16 in/out, cp.async double-buffered K/V tiles.
// 256 threads = 8 warps; 128 q rows per CTA (16/warp); 64-key tiles.
// Q is pre-scaled by 1/8 in the Q-projection epilogue.
// ---------------------------------------------------------------------------
#define AST 72
#define NKT (SEQ / 64)   // 32

// smem halves: Qs 128*72, Ks[2] 64*72, Vs[2] 64*72, Ps 128*72
#define ASM_Q  0
#define ASM_K0 (128 * AST)
#define ASM_K1 (ASM_K0 + 64 * AST)
#define ASM_V0 (ASM_K1 + 64 * AST)
#define ASM_V1 (ASM_V0 + 64 * AST)
#define ASM_P  (ASM_V1 + 64 * AST)
#define ASM_TOTAL ((ASM_P + 128 * AST) * 2)   // bytes

__global__ __launch_bounds__(256)
void attn_f16(const __half* __restrict__ Q, const __half* __restrict__ Kg,
              const __half* __restrict__ Vg, __half* __restrict__ O)
{
    extern __shared__ __half sh[];
    __half* Qs = sh + ASM_Q;
    __half* Ks[2] = { sh + ASM_K0, sh + ASM_K1 };
    __half* Vs[2] = { sh + ASM_V0, sh + ASM_V1 };
    __half* Ps = sh + ASM_P;

    const int tid  = threadIdx.x;
    const int lane = tid & 31;
    const int wrp  = tid >> 5;
    const int rA   = lane >> 2;
    const int cA   = lane & 3;
    const int b  = blockIdx.z;
    const int h  = blockIdx.y;
    const int q0 = blockIdx.x * 128;

    const __half* Qg = Q  + (size_t)(b * SEQ + q0) * DMODEL + h * DK;
    const __half* Kp = Kg + (size_t)(b * SEQ) * DMODEL + h * DK;
    const __half* Vp = Vg + (size_t)(b * SEQ) * DMODEL + h * DK;

    auto load_kv = [&](int t, int buf) {
        // 64 rows x 64 halves = 512 chunks per matrix; 2 per thread
#pragma unroll
        for (int i = 0; i < 2; i++) {
            int id = tid + i * 256;
            int r = id >> 3, c = (id & 7) << 3;
            cp16(smem_u32(&Ks[buf][r * AST + c]), Kp + (size_t)(t * 64 + r) * DMODEL + c);
        }
#pragma unroll
        for (int i = 0; i < 2; i++) {
            int id = tid + i * 256;
            int r = id >> 3, c = (id & 7) << 3;
            cp16(smem_u32(&Vs[buf][r * AST + c]), Vp + (size_t)(t * 64 + r) * DMODEL + c);
        }
        CP_COMMIT();
    };

    load_kv(0, 0);

    // Load Q tile: 128 rows x 64 halves = 1024 16B-chunks -> 4 per thread
    // (this was the R4/R5 NaN bug: only 2 iterations loaded rows 0-63)
#pragma unroll
    for (int i = 0; i < 4; i++) {
        int id = tid + i * 256;
        int r = id >> 3, c = (id & 7) << 3;
        *(uint4*)&Qs[r * AST + c] = *(const uint4*)(Qg + (size_t)r * DMODEL + c);
    }
    __syncthreads();

    // Hoist Q fragments (16 rows x 64 dims -> 4 ksteps)
    uint32_t qf[4][4];
#pragma unroll
    for (int ks = 0; ks < 4; ks++) {
        int row = wrp * 16 + (lane & 15);
        int col = ks * 16 + (lane >> 4) * 8;
        ldsm4(qf[ks], smem_u32(&Qs[row * AST + col]));
    }

    float of[8][4];
#pragma unroll
    for (int nt = 0; nt < 8; nt++)
#pragma unroll
        for (int r = 0; r < 4; r++) of[nt][r] = 0.0f;
    float m0 = -CUDART_INF_F, m1 = -CUDART_INF_F, l0 = 0.0f, l1 = 0.0f;

    for (int t = 0; t < NKT; t++) {
        const int buf = t & 1;
        if (t + 1 < NKT) { load_kv(t + 1, buf ^ 1); CP_WAIT(1); }
        else             { CP_WAIT(0); }
        __syncthreads();

        // S = Q @ K^T : 16 x 64 per warp
        float sc[8][4];
#pragma unroll
        for (int nt = 0; nt < 8; nt++)
#pragma unroll
            for (int r = 0; r < 4; r++) sc[nt][r] = 0.0f;
#pragma unroll
        for (int ks = 0; ks < 4; ks++) {
#pragma unroll
            for (int nt = 0; nt < 8; nt++) {
                uint32_t bf[2];
                int row = nt * 8 + (lane & 7);
                int col = ks * 16 + ((lane >> 3) & 1) * 8;
                ldsm2(bf, smem_u32(&Ks[buf][row * AST + col]));
                mma16816(sc[nt], qf[ks], bf);
            }
        }

        // online softmax
        float mx0 = -CUDART_INF_F, mx1 = -CUDART_INF_F;
#pragma unroll
        for (int nt = 0; nt < 8; nt++) {
            mx0 = fmaxf(mx0, fmaxf(sc[nt][0], sc[nt][1]));
            mx1 = fmaxf(mx1, fmaxf(sc[nt][2], sc[nt][3]));
        }
        mx0 = fmaxf(mx0, __shfl_xor_sync(0xffffffffu, mx0, 1));
        mx0 = fmaxf(mx0, __shfl_xor_sync(0xffffffffu, mx0, 2));
        mx1 = fmaxf(mx1, __shfl_xor_sync(0xffffffffu, mx1, 1));
        mx1 = fmaxf(mx1, __shfl_xor_sync(0xffffffffu, mx1, 2));

        float nm0 = fmaxf(m0, mx0), nm1 = fmaxf(m1, mx1);
        float corr0 = __expf(m0 - nm0), corr1 = __expf(m1 - nm1);
        float s0 = 0.0f, s1 = 0.0f;
#pragma unroll
        for (int nt = 0; nt < 8; nt++) {
            float p0 = __expf(sc[nt][0] - nm0);
            float p1 = __expf(sc[nt][1] - nm0);
            float p2 = __expf(sc[nt][2] - nm1);
            float p3 = __expf(sc[nt][3] - nm1);
            s0 += p0 + p1; s1 += p2 + p3;
            int col = nt * 8 + 2 * cA;
            *(uint32_t*)&Ps[(wrp * 16 + rA) * AST + col]     = pack_half2(p0, p1);
            *(uint32_t*)&Ps[(wrp * 16 + 8 + rA) * AST + col] = pack_half2(p2, p3);
        }
        s0 += __shfl_xor_sync(0xffffffffu, s0, 1);
        s0 += __shfl_xor_sync(0xffffffffu, s0, 2);
        s1 += __shfl_xor_sync(0xffffffffu, s1, 1);
        s1 += __shfl_xor_sync(0xffffffffu, s1, 2);
        l0 = l0 * corr0 + s0;
        l1 = l1 * corr1 + s1;
        m0 = nm0; m1 = nm1;
#pragma unroll
        for (int nt = 0; nt < 8; nt++) {
            of[nt][0] *= corr0; of[nt][1] *= corr0;
            of[nt][2] *= corr1; of[nt][3] *= corr1;
        }
        __syncwarp();

        // O += P @ V
#pragma unroll
        for (int ks = 0; ks < 4; ks++) {
            uint32_t af[4];
            int prow = wrp * 16 + (lane & 15);
            int pcol = ks * 16 + (lane >> 4) * 8;
            ldsm4(af, smem_u32(&Ps[prow * AST + pcol]));
#pragma unroll
            for (int nt = 0; nt < 8; nt++) {
                uint32_t bf[2];
                int vrow = ks * 16 + (lane & 15);
                ldsm2t(bf, smem_u32(&Vs[buf][vrow * AST + nt * 8]));
                mma16816(of[nt], af, bf);
            }
        }
        __syncthreads();   // Ps reuse + K/V buf handoff
    }

    // normalize, write fp16 ctx
    float inv0 = 1.0f / l0, inv1 = 1.0f / l1;
    __half* Op = O + (size_t)(b * SEQ + q0 + wrp * 16) * DMODEL + h * DK;
#pragma unroll
    for (int nt = 0; nt < 8; nt++) {
        int col = nt * 8 + 2 * cA;
        *(uint32_t*)&Op[(size_t)rA * DMODEL + col] =
            pack_half2(of[nt][0] * inv0, of[nt][1] * inv0);
        *(uint32_t*)&Op[(size_t)(rA + 8) * DMODEL + col] =
            pack_half2(of[nt][2] * inv1, of[nt][3] * inv1);
    }
}

// ---------------------------------------------------------------------------
// Launch
// ---------------------------------------------------------------------------
extern "C" void kernel_launch(void* const* d_in, const int* in_sizes, int n_in,
                              void* d_out, int out_size)
{
    const float* query = (const float*)d_in[0];
    const float* key_  = (const float*)d_in[1];
    const float* value = (const float*)d_in[2];
    const float* w_q   = (const float*)d_in[3];
    const float* w_k   = (const float*)d_in[4];
    const float* w_v   = (const float*)d_in[5];
    const float* w_o   = (const float*)d_in[6];
    const float* b_o   = (const float*)d_in[7];
    float* out = (float*)d_out;

    __half *qx, *kx, *vx, *wq, *wk, *wv, *wo, *Qh, *Kh, *Vh, *Ch;
    cudaGetSymbolAddress((void**)&qx, g_qx);
    cudaGetSymbolAddress((void**)&kx, g_kx);
    cudaGetSymbolAddress((void**)&vx, g_vx);
    cudaGetSymbolAddress((void**)&wq, g_wq);
    cudaGetSymbolAddress((void**)&wk, g_wk);
    cudaGetSymbolAddress((void**)&wv, g_wv);
    cudaGetSymbolAddress((void**)&wo, g_wo);
    cudaGetSymbolAddress((void**)&Qh, g_Qh);
    cudaGetSymbolAddress((void**)&Kh, g_Kh);
    cudaGetSymbolAddress((void**)&Vh, g_Vh);
    cudaGetSymbolAddress((void**)&Ch, g_Ch);

    // convert inputs + weights to fp16
    const int NIN = MROWS * DMODEL / 4;
    const int NW  = DMODEL * DMODEL / 4;
    cvt16<<<(NIN + 255) / 256, 256>>>(query, qx, NIN);
    cvt16<<<(NIN + 255) / 256, 256>>>(key_,  kx, NIN);
    cvt16<<<(NIN + 255) / 256, 256>>>(value, vx, NIN);
    cvt16<<<(NW + 255) / 256, 256>>>(w_q, wq, NW);
    cvt16<<<(NW + 255) / 256, 256>>>(w_k, wk, NW);
    cvt16<<<(NW + 255) / 256, 256>>>(w_v, wv, NW);
    cvt16<<<(NW + 255) / 256, 256>>>(w_o, wo, NW);

    cudaFuncSetAttribute(gemm_f16<true>,  cudaFuncAttributeMaxDynamicSharedMemorySize, GSM_TOTAL);
    cudaFuncSetAttribute(gemm_f16<false>, cudaFuncAttributeMaxDynamicSharedMemorySize, GSM_TOTAL);
    cudaFuncSetAttribute(attn_f16, cudaFuncAttributeMaxDynamicSharedMemorySize, ASM_TOTAL);

    dim3 gg(DMODEL / BN, MROWS / BM);  // (8, 64)
    gemm_f16<true><<<gg, 256, GSM_TOTAL>>>(qx, wq, nullptr, Qh, MROWS, DMODEL, DMODEL, 0.125f);
    gemm_f16<true><<<gg, 256, GSM_TOTAL>>>(kx, wk, nullptr, Kh, MROWS, DMODEL, DMODEL, 1.0f);
    gemm_f16<true><<<gg, 256, GSM_TOTAL>>>(vx, wv, nullptr, Vh, MROWS, DMODEL, DMODEL, 1.0f);

    attn_f16<<<dim3(SEQ / 128, NHEAD, BATCH), 256, ASM_TOTAL>>>(Qh, Kh, Vh, Ch);

    gemm_f16<false><<<gg, 256, GSM_TOTAL>>>(Ch, wo, b_o, out, MROWS, DMODEL, DMODEL, 1.0f);
}

// round 8
// speedup vs baseline: 6.8493x; 1.0195x over previous
#include <cuda_runtime.h>
#include <cuda_fp16.h>
#include <math_constants.h>
#include <cstdint>

// Problem constants
#define BATCH 4
#define SEQ   2048
#define DMODEL 1024
#define NHEAD 16
#define DK    64
#define MROWS (BATCH * SEQ)   // 8192

// ---------------------------------------------------------------------------
// Scratch (static __device__ arrays; no allocations allowed)
// ---------------------------------------------------------------------------
__device__ __half g_qx[MROWS * DMODEL];
__device__ __half g_kx[MROWS * DMODEL];
__device__ __half g_vx[MROWS * DMODEL];
__device__ __half g_wq[DMODEL * DMODEL];
__device__ __half g_wk[DMODEL * DMODEL];
__device__ __half g_wv[DMODEL * DMODEL];
__device__ __half g_wo[DMODEL * DMODEL];
__device__ __half g_Qh[MROWS * DMODEL];
__device__ __half g_Kh[MROWS * DMODEL];
__device__ __half g_Vh[MROWS * DMODEL];
__device__ __half g_Ch[MROWS * DMODEL];

// ---------------------------------------------------------------------------
// Helpers
// ---------------------------------------------------------------------------
__device__ __forceinline__ uint32_t smem_u32(const void* p) {
    uint32_t a;
    asm("{ .reg .u64 t; cvta.to.shared.u64 t, %1; cvt.u32.u64 %0, t; }" : "=r"(a) : "l"(p));
    return a;
}
__device__ __forceinline__ uint32_t pack_half2(float a, float b) {
    __half2 h = __floats2half2_rn(a, b);
    return *reinterpret_cast<uint32_t*>(&h);
}
__device__ __forceinline__ void cp16(uint32_t dst, const void* src) {
    asm volatile("cp.async.cg.shared.global [%0], [%1], 16;" :: "r"(dst), "l"(src));
}
#define CP_COMMIT() asm volatile("cp.async.commit_group;" ::: "memory")
#define CP_WAIT(n)  asm volatile("cp.async.wait_group %0;" :: "n"(n) : "memory")

__device__ __forceinline__ void ldsm4(uint32_t* r, uint32_t addr) {
    asm volatile("ldmatrix.sync.aligned.m8n8.x4.shared.b16 {%0,%1,%2,%3}, [%4];"
                 : "=r"(r[0]), "=r"(r[1]), "=r"(r[2]), "=r"(r[3]) : "r"(addr));
}
__device__ __forceinline__ void ldsm4t(uint32_t* r, uint32_t addr) {
    asm volatile("ldmatrix.sync.aligned.m8n8.x4.trans.shared.b16 {%0,%1,%2,%3}, [%4];"
                 : "=r"(r[0]), "=r"(r[1]), "=r"(r[2]), "=r"(r[3]) : "r"(addr));
}
__device__ __forceinline__ void mma16816(float* c, const uint32_t* a, uint32_t b0, uint32_t b1) {
    asm volatile(
        "mma.sync.aligned.m16n8k16.row.col.f32.f16.f16.f32 "
        "{%0,%1,%2,%3}, {%4,%5,%6,%7}, {%8,%9}, {%0,%1,%2,%3};"
        : "+f"(c[0]), "+f"(c[1]), "+f"(c[2]), "+f"(c[3])
        : "r"(a[0]), "r"(a[1]), "r"(a[2]), "r"(a[3]), "r"(b0), "r"(b1));
}

// ---------------------------------------------------------------------------
// fp32 -> fp16 conversion (fused over tensors via blockIdx.y; 2 float4/thread)
// ---------------------------------------------------------------------------
struct CvtArgs { const float* s[4]; __half* d[4]; };

__global__ __launch_bounds__(256)
void cvt16m(CvtArgs a, int n4)
{
    const float* s = a.s[blockIdx.y];
    __half* d = a.d[blockIdx.y];
    int i0 = blockIdx.x * 512 + threadIdx.x;
    int i1 = i0 + 256;
    float4 v0 = *(const float4*)(s + (size_t)i0 * 4);
    float4 v1 = *(const float4*)(s + (size_t)i1 * 4);
    uint2 h0, h1;
    h0.x = pack_half2(v0.x, v0.y); h0.y = pack_half2(v0.z, v0.w);
    h1.x = pack_half2(v1.x, v1.y); h1.y = pack_half2(v1.z, v1.w);
    *(uint2*)(d + (size_t)i0 * 4) = h0;
    *(uint2*)(d + (size_t)i1 * 4) = h1;
}

// ---------------------------------------------------------------------------
// FP16 GEMM body (NT): C[m][n] = alpha*sum_k A[m][k]*W[n][k] (+bias[n])
// BM=BN=128, BK=64; 256 thr = 8 warps (2x4), warp tile 64x32.
// cp.async double-buffered; B fragments via paired ldsm4.
// ---------------------------------------------------------------------------
#define BM 128
#define BN 128
#define BK 64
#define KST 72   // half-unit row stride (144B)
#define GSM_BUF (BM * KST)
#define GSM_TOTAL (4 * GSM_BUF * 2)

template<bool F16OUT>
__device__ __forceinline__
void gemm_body(const __half* __restrict__ A, const __half* __restrict__ W,
               const float* __restrict__ bias, void* __restrict__ Cout,
               int N, int K, float alpha, __half* sh, int bx, int by)
{
    __half* As[2] = { sh, sh + GSM_BUF };
    __half* Bs[2] = { sh + 2 * GSM_BUF, sh + 3 * GSM_BUF };

    const int tid  = threadIdx.x;
    const int lane = tid & 31;
    const int wid  = tid >> 5;
    const int wm   = wid >> 2;   // 0..1
    const int wn   = wid & 3;    // 0..3

    const __half* Ap = A + (size_t)(by * BM) * K;
    const __half* Wp = W + (size_t)(bx * BN) * K;

    float acc[4][4][4];
#pragma unroll
    for (int mt = 0; mt < 4; mt++)
#pragma unroll
        for (int nt = 0; nt < 4; nt++)
#pragma unroll
            for (int r = 0; r < 4; r++) acc[mt][nt][r] = 0.0f;

    const int nslab = K / BK;  // 16
    auto load_tile = [&](int slab, int buf) {
#pragma unroll
        for (int i = 0; i < 4; i++) {
            int id = tid + i * 256;
            int r = id >> 3, c = (id & 7) << 3;
            cp16(smem_u32(&As[buf][r * KST + c]), Ap + (size_t)r * K + slab * BK + c);
        }
#pragma unroll
        for (int i = 0; i < 4; i++) {
            int id = tid + i * 256;
            int r = id >> 3, c = (id & 7) << 3;
            cp16(smem_u32(&Bs[buf][r * KST + c]), Wp + (size_t)r * K + slab * BK + c);
        }
        CP_COMMIT();
    };

    load_tile(0, 0);
    load_tile(1, 1);

    for (int s = 0; s < nslab; s++) {
        const int buf = s & 1;
        if (s + 1 < nslab) CP_WAIT(1); else CP_WAIT(0);
        __syncthreads();

#pragma unroll
        for (int ks = 0; ks < 4; ks++) {
            uint32_t af[4][4], bq[2][4];
#pragma unroll
            for (int mt = 0; mt < 4; mt++) {
                int row = wm * 64 + mt * 16 + (lane & 15);
                int col = ks * 16 + (lane >> 4) * 8;
                ldsm4(af[mt], smem_u32(&As[buf][row * KST + col]));
            }
            // paired B: one ldsm4 covers n=16 (two fragments {r0,r2},{r1,r3})
#pragma unroll
            for (int ntp = 0; ntp < 2; ntp++) {
                int row = wn * 32 + ntp * 16 + (lane & 15);
                int col = ks * 16 + (lane >> 4) * 8;
                ldsm4(bq[ntp], smem_u32(&Bs[buf][row * KST + col]));
            }
#pragma unroll
            for (int mt = 0; mt < 4; mt++)
#pragma unroll
                for (int ntp = 0; ntp < 2; ntp++) {
                    mma16816(acc[mt][ntp * 2],     af[mt], bq[ntp][0], bq[ntp][2]);
                    mma16816(acc[mt][ntp * 2 + 1], af[mt], bq[ntp][1], bq[ntp][3]);
                }
        }
        __syncthreads();
        if (s + 2 < nslab) load_tile(s + 2, buf);
    }

    // epilogue
    const int rA = lane >> 2, cA = lane & 3;
#pragma unroll
    for (int mt = 0; mt < 4; mt++) {
        int row = by * BM + wm * 64 + mt * 16 + rA;
#pragma unroll
        for (int nt = 0; nt < 4; nt++) {
            int col = bx * BN + wn * 32 + nt * 8 + 2 * cA;
            if (F16OUT) {
                __half* C = (__half*)Cout;
                *(uint32_t*)&C[(size_t)row * N + col] =
                    pack_half2(acc[mt][nt][0] * alpha, acc[mt][nt][1] * alpha);
                *(uint32_t*)&C[(size_t)(row + 8) * N + col] =
                    pack_half2(acc[mt][nt][2] * alpha, acc[mt][nt][3] * alpha);
            } else {
                float* C = (float*)Cout;
                float b0 = bias ? bias[col] : 0.0f;
                float b1 = bias ? bias[col + 1] : 0.0f;
                float2 v0 = { acc[mt][nt][0] + b0, acc[mt][nt][1] + b1 };
                float2 v1 = { acc[mt][nt][2] + b0, acc[mt][nt][3] + b1 };
                *(float2*)&C[(size_t)row * N + col]       = v0;
                *(float2*)&C[(size_t)(row + 8) * N + col] = v1;
            }
        }
    }
}

// Fused Q/K/V projection: blockIdx.z selects (A, W, C, alpha)
struct QKVArgs {
    const __half* A[3];
    const __half* W[3];
    __half* C[3];
    float alpha[3];
};

__global__ __launch_bounds__(256)
void gemm_qkv(QKVArgs args)
{
    extern __shared__ __half sh[];
    int z = blockIdx.z;
    gemm_body<true>(args.A[z], args.W[z], nullptr, args.C[z],
                    DMODEL, DMODEL, args.alpha[z], sh, blockIdx.x, blockIdx.y);
}

__global__ __launch_bounds__(256)
void gemm_out(const __half* __restrict__ A, const __half* __restrict__ W,
              const float* __restrict__ bias, float* __restrict__ C)
{
    extern __shared__ __half sh[];
    gemm_body<false>(A, W, bias, C, DMODEL, DMODEL, 1.0f, sh, blockIdx.x, blockIdx.y);
}

// ---------------------------------------------------------------------------
// Flash attention, fp16 in/out, cp.async double-buffered K/V tiles.
// 256 threads = 8 warps; 128 q rows per CTA; 64-key tiles.
// Paired ldsm4 for K and V fragments.
// ---------------------------------------------------------------------------
#define AST 72
#define NKT (SEQ / 64)   // 32

#define ASM_Q  0
#define ASM_K0 (128 * AST)
#define ASM_K1 (ASM_K0 + 64 * AST)
#define ASM_V0 (ASM_K1 + 64 * AST)
#define ASM_V1 (ASM_V0 + 64 * AST)
#define ASM_P  (ASM_V1 + 64 * AST)
#define ASM_TOTAL ((ASM_P + 128 * AST) * 2)

__global__ __launch_bounds__(256)
void attn_f16(const __half* __restrict__ Q, const __half* __restrict__ Kg,
              const __half* __restrict__ Vg, __half* __restrict__ O)
{
    extern __shared__ __half sh[];
    __half* Qs = sh + ASM_Q;
    __half* Ks[2] = { sh + ASM_K0, sh + ASM_K1 };
    __half* Vs[2] = { sh + ASM_V0, sh + ASM_V1 };
    __half* Ps = sh + ASM_P;

    const int tid  = threadIdx.x;
    const int lane = tid & 31;
    const int wrp  = tid >> 5;
    const int rA   = lane >> 2;
    const int cA   = lane & 3;
    const int b  = blockIdx.z;
    const int h  = blockIdx.y;
    const int q0 = blockIdx.x * 128;

    const __half* Qg = Q  + (size_t)(b * SEQ + q0) * DMODEL + h * DK;
    const __half* Kp = Kg + (size_t)(b * SEQ) * DMODEL + h * DK;
    const __half* Vp = Vg + (size_t)(b * SEQ) * DMODEL + h * DK;

    auto load_kv = [&](int t, int buf) {
#pragma unroll
        for (int i = 0; i < 2; i++) {
            int id = tid + i * 256;
            int r = id >> 3, c = (id & 7) << 3;
            cp16(smem_u32(&Ks[buf][r * AST + c]), Kp + (size_t)(t * 64 + r) * DMODEL + c);
        }
#pragma unroll
        for (int i = 0; i < 2; i++) {
            int id = tid + i * 256;
            int r = id >> 3, c = (id & 7) << 3;
            cp16(smem_u32(&Vs[buf][r * AST + c]), Vp + (size_t)(t * 64 + r) * DMODEL + c);
        }
        CP_COMMIT();
    };

    load_kv(0, 0);

    // Q tile: 128 rows x 64 halves = 1024 16B-chunks -> 4/thread
#pragma unroll
    for (int i = 0; i < 4; i++) {
        int id = tid + i * 256;
        int r = id >> 3, c = (id & 7) << 3;
        *(uint4*)&Qs[r * AST + c] = *(const uint4*)(Qg + (size_t)r * DMODEL + c);
    }
    __syncthreads();

    uint32_t qf[4][4];
#pragma unroll
    for (int ks = 0; ks < 4; ks++) {
        int row = wrp * 16 + (lane & 15);
        int col = ks * 16 + (lane >> 4) * 8;
        ldsm4(qf[ks], smem_u32(&Qs[row * AST + col]));
    }

    float of[8][4];
#pragma unroll
    for (int nt = 0; nt < 8; nt++)
#pragma unroll
        for (int r = 0; r < 4; r++) of[nt][r] = 0.0f;
    float m0 = -CUDART_INF_F, m1 = -CUDART_INF_F, l0 = 0.0f, l1 = 0.0f;

    for (int t = 0; t < NKT; t++) {
        const int buf = t & 1;
        if (t + 1 < NKT) { load_kv(t + 1, buf ^ 1); CP_WAIT(1); }
        else             { CP_WAIT(0); }
        __syncthreads();

        // S = Q @ K^T : paired K fragments (one ldsm4 -> two n8 frags)
        float sc[8][4];
#pragma unroll
        for (int nt = 0; nt < 8; nt++)
#pragma unroll
            for (int r = 0; r < 4; r++) sc[nt][r] = 0.0f;
#pragma unroll
        for (int ks = 0; ks < 4; ks++) {
#pragma unroll
            for (int ntp = 0; ntp < 4; ntp++) {
                uint32_t kb[4];
                int row = ntp * 16 + (lane & 15);
                int col = ks * 16 + (lane >> 4) * 8;
                ldsm4(kb, smem_u32(&Ks[buf][row * AST + col]));
                mma16816(sc[ntp * 2],     qf[ks], kb[0], kb[2]);
                mma16816(sc[ntp * 2 + 1], qf[ks], kb[1], kb[3]);
            }
        }

        // online softmax
        float mx0 = -CUDART_INF_F, mx1 = -CUDART_INF_F;
#pragma unroll
        for (int nt = 0; nt < 8; nt++) {
            mx0 = fmaxf(mx0, fmaxf(sc[nt][0], sc[nt][1]));
            mx1 = fmaxf(mx1, fmaxf(sc[nt][2], sc[nt][3]));
        }
        mx0 = fmaxf(mx0, __shfl_xor_sync(0xffffffffu, mx0, 1));
        mx0 = fmaxf(mx0, __shfl_xor_sync(0xffffffffu, mx0, 2));
        mx1 = fmaxf(mx1, __shfl_xor_sync(0xffffffffu, mx1, 1));
        mx1 = fmaxf(mx1, __shfl_xor_sync(0xffffffffu, mx1, 2));

        float nm0 = fmaxf(m0, mx0), nm1 = fmaxf(m1, mx1);
        float corr0 = __expf(m0 - nm0), corr1 = __expf(m1 - nm1);
        float s0 = 0.0f, s1 = 0.0f;
#pragma unroll
        for (int nt = 0; nt < 8; nt++) {
            float p0 = __expf(sc[nt][0] - nm0);
            float p1 = __expf(sc[nt][1] - nm0);
            float p2 = __expf(sc[nt][2] - nm1);
            float p3 = __expf(sc[nt][3] - nm1);
            s0 += p0 + p1; s1 += p2 + p3;
            int col = nt * 8 + 2 * cA;
            *(uint32_t*)&Ps[(wrp * 16 + rA) * AST + col]     = pack_half2(p0, p1);
            *(uint32_t*)&Ps[(wrp * 16 + 8 + rA) * AST + col] = pack_half2(p2, p3);
        }
        s0 += __shfl_xor_sync(0xffffffffu, s0, 1);
        s0 += __shfl_xor_sync(0xffffffffu, s0, 2);
        s1 += __shfl_xor_sync(0xffffffffu, s1, 1);
        s1 += __shfl_xor_sync(0xffffffffu, s1, 2);
        l0 = l0 * corr0 + s0;
        l1 = l1 * corr1 + s1;
        m0 = nm0; m1 = nm1;
#pragma unroll
        for (int nt = 0; nt < 8; nt++) {
            of[nt][0] *= corr0; of[nt][1] *= corr0;
            of[nt][2] *= corr1; of[nt][3] *= corr1;
        }
        __syncwarp();

        // O += P @ V : paired V fragments (one ldsm4t -> two n8 frags)
#pragma unroll
        for (int ks = 0; ks < 4; ks++) {
            uint32_t af[4];
            int prow = wrp * 16 + (lane & 15);
            int pcol = ks * 16 + (lane >> 4) * 8;
            ldsm4(af, smem_u32(&Ps[prow * AST + pcol]));
#pragma unroll
            for (int ntp = 0; ntp < 4; ntp++) {
                uint32_t vb[4];
                int vrow = ks * 16 + (lane & 15);
                int vcol = ntp * 16 + (lane >> 4) * 8;
                ldsm4t(vb, smem_u32(&Vs[buf][vrow * AST + vcol]));
                mma16816(of[ntp * 2],     af, vb[0], vb[1]);
                mma16816(of[ntp * 2 + 1], af, vb[2], vb[3]);
            }
        }
        __syncthreads();
    }

    // normalize, write fp16 ctx
    float inv0 = 1.0f / l0, inv1 = 1.0f / l1;
    __half* Op = O + (size_t)(b * SEQ + q0 + wrp * 16) * DMODEL + h * DK;
#pragma unroll
    for (int nt = 0; nt < 8; nt++) {
        int col = nt * 8 + 2 * cA;
        *(uint32_t*)&Op[(size_t)rA * DMODEL + col] =
            pack_half2(of[nt][0] * inv0, of[nt][1] * inv0);
        *(uint32_t*)&Op[(size_t)(rA + 8) * DMODEL + col] =
            pack_half2(of[nt][2] * inv1, of[nt][3] * inv1);
    }
}

// ---------------------------------------------------------------------------
// Launch
// ---------------------------------------------------------------------------
extern "C" void kernel_launch(void* const* d_in, const int* in_sizes, int n_in,
                              void* d_out, int out_size)
{
    const float* query = (const float*)d_in[0];
    const float* key_  = (const float*)d_in[1];
    const float* value = (const float*)d_in[2];
    const float* w_q   = (const float*)d_in[3];
    const float* w_k   = (const float*)d_in[4];
    const float* w_v   = (const float*)d_in[5];
    const float* w_o   = (const float*)d_in[6];
    const float* b_o   = (const float*)d_in[7];
    float* out = (float*)d_out;

    __half *qx, *kx, *vx, *wq, *wk, *wv, *wo, *Qh, *Kh, *Vh, *Ch;
    cudaGetSymbolAddress((void**)&qx, g_qx);
    cudaGetSymbolAddress((void**)&kx, g_kx);
    cudaGetSymbolAddress((void**)&vx, g_vx);
    cudaGetSymbolAddress((void**)&wq, g_wq);
    cudaGetSymbolAddress((void**)&wk, g_wk);
    cudaGetSymbolAddress((void**)&wv, g_wv);
    cudaGetSymbolAddress((void**)&wo, g_wo);
    cudaGetSymbolAddress((void**)&Qh, g_Qh);
    cudaGetSymbolAddress((void**)&Kh, g_Kh);
    cudaGetSymbolAddress((void**)&Vh, g_Vh);
    cudaGetSymbolAddress((void**)&Ch, g_Ch);

    // fused converts: inputs (3 tensors), weights (4 tensors)
    const int NIN = MROWS * DMODEL / 4;   // float4 count per input
    const int NW  = DMODEL * DMODEL / 4;
    CvtArgs ia = {{query, key_, value, nullptr}, {qx, kx, vx, nullptr}};
    CvtArgs wa = {{w_q, w_k, w_v, w_o}, {wq, wk, wv, wo}};
    cvt16m<<<dim3(NIN / 512, 3), 256>>>(ia, NIN);
    cvt16m<<<dim3(NW / 512, 4), 256>>>(wa, NW);

    cudaFuncSetAttribute(gemm_qkv, cudaFuncAttributeMaxDynamicSharedMemorySize, GSM_TOTAL);
    cudaFuncSetAttribute(gemm_out, cudaFuncAttributeMaxDynamicSharedMemorySize, GSM_TOTAL);
    cudaFuncSetAttribute(attn_f16, cudaFuncAttributeMaxDynamicSharedMemorySize, ASM_TOTAL);

    // fused Q/K/V projections (Q pre-scaled by 1/8)
    QKVArgs qa;
    qa.A[0] = qx; qa.A[1] = kx; qa.A[2] = vx;
    qa.W[0] = wq; qa.W[1] = wk; qa.W[2] = wv;
    qa.C[0] = Qh; qa.C[1] = Kh; qa.C[2] = Vh;
    qa.alpha[0] = 0.125f; qa.alpha[1] = 1.0f; qa.alpha[2] = 1.0f;
    gemm_qkv<<<dim3(DMODEL / BN, MROWS / BM, 3), 256, GSM_TOTAL>>>(qa);

    attn_f16<<<dim3(SEQ / 128, NHEAD, BATCH), 256, ASM_TOTAL>>>(Qh, Kh, Vh, Ch);

    gemm_out<<<dim3(DMODEL / BN, MROWS / BM), 256, GSM_TOTAL>>>(Ch, wo, b_o, out);
}

// round 9
// speedup vs baseline: 7.1751x; 1.0476x over previous
#include <cuda_runtime.h>
#include <cuda_fp16.h>
#include <math_constants.h>
#include <cstdint>

// Problem constants
#define BATCH 4
#define SEQ   2048
#define DMODEL 1024
#define NHEAD 16
#define DK    64
#define MROWS (BATCH * SEQ)   // 8192

// ---------------------------------------------------------------------------
// Scratch (static __device__ arrays; no allocations allowed)
// ---------------------------------------------------------------------------
__device__ __half g_qx[MROWS * DMODEL];
__device__ __half g_kx[MROWS * DMODEL];
__device__ __half g_vx[MROWS * DMODEL];
__device__ __half g_wq[DMODEL * DMODEL];
__device__ __half g_wk[DMODEL * DMODEL];
__device__ __half g_wv[DMODEL * DMODEL];
__device__ __half g_wo[DMODEL * DMODEL];
__device__ __half g_Qh[MROWS * DMODEL];
__device__ __half g_Kh[MROWS * DMODEL];
__device__ __half g_Vh[MROWS * DMODEL];
__device__ __half g_Ch[MROWS * DMODEL];

// ---------------------------------------------------------------------------
// Helpers
// ---------------------------------------------------------------------------
__device__ __forceinline__ uint32_t smem_u32(const void* p) {
    uint32_t a;
    asm("{ .reg .u64 t; cvta.to.shared.u64 t, %1; cvt.u32.u64 %0, t; }" : "=r"(a) : "l"(p));
    return a;
}
__device__ __forceinline__ uint32_t pack_half2(float a, float b) {
    __half2 h = __floats2half2_rn(a, b);
    return *reinterpret_cast<uint32_t*>(&h);
}
__device__ __forceinline__ float ex2(float x) {
    float r;
    asm("ex2.approx.f32 %0, %1;" : "=f"(r) : "f"(x));
    return r;
}
__device__ __forceinline__ void cp16(uint32_t dst, const void* src) {
    asm volatile("cp.async.cg.shared.global [%0], [%1], 16;" :: "r"(dst), "l"(src));
}
#define CP_COMMIT() asm volatile("cp.async.commit_group;" ::: "memory")
#define CP_WAIT(n)  asm volatile("cp.async.wait_group %0;" :: "n"(n) : "memory")

__device__ __forceinline__ void ldsm4(uint32_t* r, uint32_t addr) {
    asm volatile("ldmatrix.sync.aligned.m8n8.x4.shared.b16 {%0,%1,%2,%3}, [%4];"
                 : "=r"(r[0]), "=r"(r[1]), "=r"(r[2]), "=r"(r[3]) : "r"(addr));
}
__device__ __forceinline__ void ldsm4t(uint32_t* r, uint32_t addr) {
    asm volatile("ldmatrix.sync.aligned.m8n8.x4.trans.shared.b16 {%0,%1,%2,%3}, [%4];"
                 : "=r"(r[0]), "=r"(r[1]), "=r"(r[2]), "=r"(r[3]) : "r"(addr));
}
__device__ __forceinline__ void mma16816(float* c, const uint32_t* a, uint32_t b0, uint32_t b1) {
    asm volatile(
        "mma.sync.aligned.m16n8k16.row.col.f32.f16.f16.f32 "
        "{%0,%1,%2,%3}, {%4,%5,%6,%7}, {%8,%9}, {%0,%1,%2,%3};"
        : "+f"(c[0]), "+f"(c[1]), "+f"(c[2]), "+f"(c[3])
        : "r"(a[0]), "r"(a[1]), "r"(a[2]), "r"(a[3]), "r"(b0), "r"(b1));
}

// ---------------------------------------------------------------------------
// fp32 -> fp16 conversion (fused over tensors via blockIdx.y; 2 float4/thread)
// ---------------------------------------------------------------------------
struct CvtArgs { const float* s[4]; __half* d[4]; };

__global__ __launch_bounds__(256)
void cvt16m(CvtArgs a, int n4)
{
    const float* s = a.s[blockIdx.y];
    __half* d = a.d[blockIdx.y];
    int i0 = blockIdx.x * 512 + threadIdx.x;
    int i1 = i0 + 256;
    float4 v0 = *(const float4*)(s + (size_t)i0 * 4);
    float4 v1 = *(const float4*)(s + (size_t)i1 * 4);
    uint2 h0, h1;
    h0.x = pack_half2(v0.x, v0.y); h0.y = pack_half2(v0.z, v0.w);
    h1.x = pack_half2(v1.x, v1.y); h1.y = pack_half2(v1.z, v1.w);
    *(uint2*)(d + (size_t)i0 * 4) = h0;
    *(uint2*)(d + (size_t)i1 * 4) = h1;
}

// ---------------------------------------------------------------------------
// FP16 GEMM body (NT): unchanged from R7 (known-good).
// ---------------------------------------------------------------------------
#define BM 128
#define BN 128
#define BK 64
#define KST 72
#define GSM_BUF (BM * KST)
#define GSM_TOTAL (4 * GSM_BUF * 2)

template<bool F16OUT>
__device__ __forceinline__
void gemm_body(const __half* __restrict__ A, const __half* __restrict__ W,
               const float* __restrict__ bias, void* __restrict__ Cout,
               int N, int K, float alpha, __half* sh, int bx, int by)
{
    __half* As[2] = { sh, sh + GSM_BUF };
    __half* Bs[2] = { sh + 2 * GSM_BUF, sh + 3 * GSM_BUF };

    const int tid  = threadIdx.x;
    const int lane = tid & 31;
    const int wid  = tid >> 5;
    const int wm   = wid >> 2;
    const int wn   = wid & 3;

    const __half* Ap = A + (size_t)(by * BM) * K;
    const __half* Wp = W + (size_t)(bx * BN) * K;

    float acc[4][4][4];
#pragma unroll
    for (int mt = 0; mt < 4; mt++)
#pragma unroll
        for (int nt = 0; nt < 4; nt++)
#pragma unroll
            for (int r = 0; r < 4; r++) acc[mt][nt][r] = 0.0f;

    const int nslab = K / BK;
    auto load_tile = [&](int slab, int buf) {
#pragma unroll
        for (int i = 0; i < 4; i++) {
            int id = tid + i * 256;
            int r = id >> 3, c = (id & 7) << 3;
            cp16(smem_u32(&As[buf][r * KST + c]), Ap + (size_t)r * K + slab * BK + c);
        }
#pragma unroll
        for (int i = 0; i < 4; i++) {
            int id = tid + i * 256;
            int r = id >> 3, c = (id & 7) << 3;
            cp16(smem_u32(&Bs[buf][r * KST + c]), Wp + (size_t)r * K + slab * BK + c);
        }
        CP_COMMIT();
    };

    load_tile(0, 0);
    load_tile(1, 1);

    for (int s = 0; s < nslab; s++) {
        const int buf = s & 1;
        if (s + 1 < nslab) CP_WAIT(1); else CP_WAIT(0);
        __syncthreads();

#pragma unroll
        for (int ks = 0; ks < 4; ks++) {
            uint32_t af[4][4], bq[2][4];
#pragma unroll
            for (int mt = 0; mt < 4; mt++) {
                int row = wm * 64 + mt * 16 + (lane & 15);
                int col = ks * 16 + (lane >> 4) * 8;
                ldsm4(af[mt], smem_u32(&As[buf][row * KST + col]));
            }
#pragma unroll
            for (int ntp = 0; ntp < 2; ntp++) {
                int row = wn * 32 + ntp * 16 + (lane & 15);
                int col = ks * 16 + (lane >> 4) * 8;
                ldsm4(bq[ntp], smem_u32(&Bs[buf][row * KST + col]));
            }
#pragma unroll
            for (int mt = 0; mt < 4; mt++)
#pragma unroll
                for (int ntp = 0; ntp < 2; ntp++) {
                    mma16816(acc[mt][ntp * 2],     af[mt], bq[ntp][0], bq[ntp][2]);
                    mma16816(acc[mt][ntp * 2 + 1], af[mt], bq[ntp][1], bq[ntp][3]);
                }
        }
        __syncthreads();
        if (s + 2 < nslab) load_tile(s + 2, buf);
    }

    const int rA = lane >> 2, cA = lane & 3;
#pragma unroll
    for (int mt = 0; mt < 4; mt++) {
        int row = by * BM + wm * 64 + mt * 16 + rA;
#pragma unroll
        for (int nt = 0; nt < 4; nt++) {
            int col = bx * BN + wn * 32 + nt * 8 + 2 * cA;
            if (F16OUT) {
                __half* C = (__half*)Cout;
                *(uint32_t*)&C[(size_t)row * N + col] =
                    pack_half2(acc[mt][nt][0] * alpha, acc[mt][nt][1] * alpha);
                *(uint32_t*)&C[(size_t)(row + 8) * N + col] =
                    pack_half2(acc[mt][nt][2] * alpha, acc[mt][nt][3] * alpha);
            } else {
                float* C = (float*)Cout;
                float b0 = bias ? bias[col] : 0.0f;
                float b1 = bias ? bias[col + 1] : 0.0f;
                float2 v0 = { acc[mt][nt][0] + b0, acc[mt][nt][1] + b1 };
                float2 v1 = { acc[mt][nt][2] + b0, acc[mt][nt][3] + b1 };
                *(float2*)&C[(size_t)row * N + col]       = v0;
                *(float2*)&C[(size_t)(row + 8) * N + col] = v1;
            }
        }
    }
}

struct QKVArgs {
    const __half* A[3];
    const __half* W[3];
    __half* C[3];
    float alpha[3];
};

__global__ __launch_bounds__(256)
void gemm_qkv(QKVArgs args)
{
    extern __shared__ __half sh[];
    int z = blockIdx.z;
    gemm_body<true>(args.A[z], args.W[z], nullptr, args.C[z],
                    DMODEL, DMODEL, args.alpha[z], sh, blockIdx.x, blockIdx.y);
}

__global__ __launch_bounds__(256)
void gemm_out(const __half* __restrict__ A, const __half* __restrict__ W,
              const float* __restrict__ bias, float* __restrict__ C)
{
    extern __shared__ __half sh[];
    gemm_body<false>(A, W, bias, C, DMODEL, DMODEL, 1.0f, sh, blockIdx.x, blockIdx.y);
}

// ---------------------------------------------------------------------------
// Flash attention v2-style: P kept in registers (S C-frag == PV A-frag),
// exp2-domain softmax (Q pre-scaled by 0.125*log2e), one sync per k-tile.
// 256 threads = 8 warps; 128 q rows per CTA; 64-key tiles.
// ---------------------------------------------------------------------------
#define AST 72
#define NKT (SEQ / 64)   // 32

// smem halves: Qs 128*72, Ks[2] 64*72, Vs[2] 64*72  (no Ps)
#define ASM_Q  0
#define ASM_K0 (128 * AST)
#define ASM_K1 (ASM_K0 + 64 * AST)
#define ASM_V0 (ASM_K1 + 64 * AST)
#define ASM_V1 (ASM_V0 + 64 * AST)
#define ASM_TOTAL ((ASM_V1 + 64 * AST) * 2)   // 55296 bytes

__global__ __launch_bounds__(256)
void attn_f16(const __half* __restrict__ Q, const __half* __restrict__ Kg,
              const __half* __restrict__ Vg, __half* __restrict__ O)
{
    extern __shared__ __half sh[];
    __half* Qs = sh + ASM_Q;
    __half* Ks[2] = { sh + ASM_K0, sh + ASM_K1 };
    __half* Vs[2] = { sh + ASM_V0, sh + ASM_V1 };

    const int tid  = threadIdx.x;
    const int lane = tid & 31;
    const int wrp  = tid >> 5;
    const int rA   = lane >> 2;
    const int cA   = lane & 3;
    const int b  = blockIdx.z;
    const int h  = blockIdx.y;
    const int q0 = blockIdx.x * 128;

    const __half* Qg = Q  + (size_t)(b * SEQ + q0) * DMODEL + h * DK;
    const __half* Kp = Kg + (size_t)(b * SEQ) * DMODEL + h * DK;
    const __half* Vp = Vg + (size_t)(b * SEQ) * DMODEL + h * DK;

    auto load_kv = [&](int t, int buf) {
#pragma unroll
        for (int i = 0; i < 2; i++) {
            int id = tid + i * 256;
            int r = id >> 3, c = (id & 7) << 3;
            cp16(smem_u32(&Ks[buf][r * AST + c]), Kp + (size_t)(t * 64 + r) * DMODEL + c);
        }
#pragma unroll
        for (int i = 0; i < 2; i++) {
            int id = tid + i * 256;
            int r = id >> 3, c = (id & 7) << 3;
            cp16(smem_u32(&Vs[buf][r * AST + c]), Vp + (size_t)(t * 64 + r) * DMODEL + c);
        }
        CP_COMMIT();
    };

    load_kv(0, 0);

    // Q tile: 128 rows x 64 halves = 1024 16B-chunks -> 4/thread
#pragma unroll
    for (int i = 0; i < 4; i++) {
        int id = tid + i * 256;
        int r = id >> 3, c = (id & 7) << 3;
        *(uint4*)&Qs[r * AST + c] = *(const uint4*)(Qg + (size_t)r * DMODEL + c);
    }
    __syncthreads();

    uint32_t qf[4][4];
#pragma unroll
    for (int ks = 0; ks < 4; ks++) {
        int row = wrp * 16 + (lane & 15);
        int col = ks * 16 + (lane >> 4) * 8;
        ldsm4(qf[ks], smem_u32(&Qs[row * AST + col]));
    }

    float of[8][4];
#pragma unroll
    for (int nt = 0; nt < 8; nt++)
#pragma unroll
        for (int r = 0; r < 4; r++) of[nt][r] = 0.0f;
    float m0 = -CUDART_INF_F, m1 = -CUDART_INF_F, l0 = 0.0f, l1 = 0.0f;

    for (int t = 0; t < NKT; t++) {
        const int buf = t & 1;
        CP_WAIT(0);          // tile t landed (issued last iteration / prologue)
        __syncthreads();     // visibility + all warps done with buf^1
        if (t + 1 < NKT) load_kv(t + 1, buf ^ 1);

        // S = Q @ K^T (scores already in log2 domain: Q pre-scaled by 1/8*log2e)
        float sc[8][4];
#pragma unroll
        for (int nt = 0; nt < 8; nt++)
#pragma unroll
            for (int r = 0; r < 4; r++) sc[nt][r] = 0.0f;
#pragma unroll
        for (int ks = 0; ks < 4; ks++) {
#pragma unroll
            for (int ntp = 0; ntp < 4; ntp++) {
                uint32_t kb[4];
                int row = ntp * 16 + (lane & 15);
                int col = ks * 16 + (lane >> 4) * 8;
                ldsm4(kb, smem_u32(&Ks[buf][row * AST + col]));
                mma16816(sc[ntp * 2],     qf[ks], kb[0], kb[2]);
                mma16816(sc[ntp * 2 + 1], qf[ks], kb[1], kb[3]);
            }
        }

        // online softmax in exp2 domain; pack P straight into A-fragments
        float mx0 = -CUDART_INF_F, mx1 = -CUDART_INF_F;
#pragma unroll
        for (int nt = 0; nt < 8; nt++) {
            mx0 = fmaxf(mx0, fmaxf(sc[nt][0], sc[nt][1]));
            mx1 = fmaxf(mx1, fmaxf(sc[nt][2], sc[nt][3]));
        }
        mx0 = fmaxf(mx0, __shfl_xor_sync(0xffffffffu, mx0, 1));
        mx0 = fmaxf(mx0, __shfl_xor_sync(0xffffffffu, mx0, 2));
        mx1 = fmaxf(mx1, __shfl_xor_sync(0xffffffffu, mx1, 1));
        mx1 = fmaxf(mx1, __shfl_xor_sync(0xffffffffu, mx1, 2));

        float nm0 = fmaxf(m0, mx0), nm1 = fmaxf(m1, mx1);
        float corr0 = ex2(m0 - nm0), corr1 = ex2(m1 - nm1);
        float s0 = 0.0f, s1 = 0.0f;
        uint32_t pf[4][4];
#pragma unroll
        for (int nt = 0; nt < 8; nt++) {
            float p0 = ex2(sc[nt][0] - nm0);
            float p1 = ex2(sc[nt][1] - nm0);
            float p2 = ex2(sc[nt][2] - nm1);
            float p3 = ex2(sc[nt][3] - nm1);
            s0 += p0 + p1; s1 += p2 + p3;
            pf[nt >> 1][(nt & 1) * 2]     = pack_half2(p0, p1);
            pf[nt >> 1][(nt & 1) * 2 + 1] = pack_half2(p2, p3);
        }
        s0 += __shfl_xor_sync(0xffffffffu, s0, 1);
        s0 += __shfl_xor_sync(0xffffffffu, s0, 2);
        s1 += __shfl_xor_sync(0xffffffffu, s1, 1);
        s1 += __shfl_xor_sync(0xffffffffu, s1, 2);
        l0 = l0 * corr0 + s0;
        l1 = l1 * corr1 + s1;
        m0 = nm0; m1 = nm1;
#pragma unroll
        for (int nt = 0; nt < 8; nt++) {
            of[nt][0] *= corr0; of[nt][1] *= corr0;
            of[nt][2] *= corr1; of[nt][3] *= corr1;
        }

        // O += P @ V  (P already in A-fragment registers)
#pragma unroll
        for (int ks = 0; ks < 4; ks++) {
#pragma unroll
            for (int ntp = 0; ntp < 4; ntp++) {
                uint32_t vb[4];
                int vrow = ks * 16 + (lane & 15);
                int vcol = ntp * 16 + (lane >> 4) * 8;
                ldsm4t(vb, smem_u32(&Vs[buf][vrow * AST + vcol]));
                mma16816(of[ntp * 2],     pf[ks], vb[0], vb[1]);
                mma16816(of[ntp * 2 + 1], pf[ks], vb[2], vb[3]);
            }
        }
    }

    // normalize, write fp16 ctx
    float inv0 = 1.0f / l0, inv1 = 1.0f / l1;
    __half* Op = O + (size_t)(b * SEQ + q0 + wrp * 16) * DMODEL + h * DK;
#pragma unroll
    for (int nt = 0; nt < 8; nt++) {
        int col = nt * 8 + 2 * cA;
        *(uint32_t*)&Op[(size_t)rA * DMODEL + col] =
            pack_half2(of[nt][0] * inv0, of[nt][1] * inv0);
        *(uint32_t*)&Op[(size_t)(rA + 8) * DMODEL + col] =
            pack_half2(of[nt][2] * inv1, of[nt][3] * inv1);
    }
}

// ---------------------------------------------------------------------------
// Launch
// ---------------------------------------------------------------------------
extern "C" void kernel_launch(void* const* d_in, const int* in_sizes, int n_in,
                              void* d_out, int out_size)
{
    const float* query = (const float*)d_in[0];
    const float* key_  = (const float*)d_in[1];
    const float* value = (const float*)d_in[2];
    const float* w_q   = (const float*)d_in[3];
    const float* w_k   = (const float*)d_in[4];
    const float* w_v   = (const float*)d_in[5];
    const float* w_o   = (const float*)d_in[6];
    const float* b_o   = (const float*)d_in[7];
    float* out = (float*)d_out;

    __half *qx, *kx, *vx, *wq, *wk, *wv, *wo, *Qh, *Kh, *Vh, *Ch;
    cudaGetSymbolAddress((void**)&qx, g_qx);
    cudaGetSymbolAddress((void**)&kx, g_kx);
    cudaGetSymbolAddress((void**)&vx, g_vx);
    cudaGetSymbolAddress((void**)&wq, g_wq);
    cudaGetSymbolAddress((void**)&wk, g_wk);
    cudaGetSymbolAddress((void**)&wv, g_wv);
    cudaGetSymbolAddress((void**)&wo, g_wo);
    cudaGetSymbolAddress((void**)&Qh, g_Qh);
    cudaGetSymbolAddress((void**)&Kh, g_Kh);
    cudaGetSymbolAddress((void**)&Vh, g_Vh);
    cudaGetSymbolAddress((void**)&Ch, g_Ch);

    const int NIN = MROWS * DMODEL / 4;
    const int NW  = DMODEL * DMODEL / 4;
    CvtArgs ia = {{query, key_, value, nullptr}, {qx, kx, vx, nullptr}};
    CvtArgs wa = {{w_q, w_k, w_v, w_o}, {wq, wk, wv, wo}};
    cvt16m<<<dim3(NIN / 512, 3), 256>>>(ia, NIN);
    cvt16m<<<dim3(NW / 512, 4), 256>>>(wa, NW);

    cudaFuncSetAttribute(gemm_qkv, cudaFuncAttributeMaxDynamicSharedMemorySize, GSM_TOTAL);
    cudaFuncSetAttribute(gemm_out, cudaFuncAttributeMaxDynamicSharedMemorySize, GSM_TOTAL);
    cudaFuncSetAttribute(attn_f16, cudaFuncAttributeMaxDynamicSharedMemorySize, ASM_TOTAL);

    // Q scaled by 1/sqrt(dk) * log2(e) so softmax can run in exp2 domain
    QKVArgs qa;
    qa.A[0] = qx; qa.A[1] = kx; qa.A[2] = vx;
    qa.W[0] = wq; qa.W[1] = wk; qa.W[2] = wv;
    qa.C[0] = Qh; qa.C[1] = Kh; qa.C[2] = Vh;
    qa.alpha[0] = 0.125f * 1.44269504088896341f; qa.alpha[1] = 1.0f; qa.alpha[2] = 1.0f;
    gemm_qkv<<<dim3(DMODEL / BN, MROWS / BM, 3), 256, GSM_TOTAL>>>(qa);

    attn_f16<<<dim3(SEQ / 128, NHEAD, BATCH), 256, ASM_TOTAL>>>(Qh, Kh, Vh, Ch);

    gemm_out<<<dim3(DMODEL / BN, MROWS / BM), 256, GSM_TOTAL>>>(Ch, wo, b_o, out);
}